// round 1
// baseline (speedup 1.0000x reference)
#include <cuda_runtime.h>
#include <math.h>

// Problem constants
#define BB 4
#define SS 2048
#define HH 1024
#define DD 64
#define MM (BB*SS)   // 8192

// Scratch (device globals; no allocation allowed)
__device__ float g_qp[MM*DD];
__device__ float g_kp[MM*DD];
__device__ float g_vp[MM*DD];
__device__ float g_Gpart[BB*16*DD*DD];
__device__ float g_Kspart[BB*16*DD];
__device__ float g_G[BB*DD*DD];
__device__ float g_Ksum[BB*DD];
__device__ float g_Weff[DD*HH];

// ---------------------------------------------------------------------------
// W_eff[d][j] = sum_h Wout[h*64+d][j]   (heads share weights -> fold tile())
// ---------------------------------------------------------------------------
__global__ void k_weff(const float* __restrict__ Wout) {
    int idx = blockIdx.x * 256 + threadIdx.x;   // 65536 total
    int d = idx >> 10, j = idx & 1023;
    float s = 0.f;
#pragma unroll
    for (int h = 0; h < 16; ++h) s += Wout[(h*DD + d)*HH + j];
    g_Weff[idx] = s;
    (void)d;
}

// ---------------------------------------------------------------------------
// Projection GEMM: out[8192,64] = X[8192,1024] @ W[1024,64] + bias
// blockIdx.y selects q/k/v.  BM=128, BN=64, BK=32, 256 threads, 8x4 microtile.
// ---------------------------------------------------------------------------
__global__ __launch_bounds__(256) void k_proj(
    const float* __restrict__ Xq, const float* __restrict__ Xk, const float* __restrict__ Xv,
    const float* __restrict__ Wq, const float* __restrict__ bq,
    const float* __restrict__ Wk, const float* __restrict__ bk,
    const float* __restrict__ Wv, const float* __restrict__ bv)
{
    const float* X; const float* W; const float* bias; float* O;
    if (blockIdx.y == 0)      { X = Xq; W = Wq; bias = bq; O = g_qp; }
    else if (blockIdx.y == 1) { X = Xk; W = Wk; bias = bk; O = g_kp; }
    else                      { X = Xv; W = Wv; bias = bv; O = g_vp; }

    __shared__ float Xs[32*132];   // [k][m], padded
    __shared__ float Ws[32*64];    // [k][n]

    const int t  = threadIdx.x;
    const int m0 = blockIdx.x * 128;
    const int ty = t >> 4, tx = t & 15;

    float acc[8][4];
#pragma unroll
    for (int i = 0; i < 8; ++i)
#pragma unroll
        for (int j = 0; j < 4; ++j) acc[i][j] = 0.f;

    float4 xr[4]; float4 wr[2];

    auto ld = [&](int kt) {
        int k0 = kt * 32;
#pragma unroll
        for (int it = 0; it < 4; ++it) {
            int id = t + it*256; int row = id >> 3, c4 = id & 7;
            xr[it] = *(const float4*)&X[(size_t)(m0+row)*HH + k0 + c4*4];
        }
#pragma unroll
        for (int it = 0; it < 2; ++it) {
            int id = t + it*256; int row = id >> 4, c4 = id & 15;
            wr[it] = *(const float4*)&W[(size_t)(k0+row)*DD + c4*4];
        }
    };
    auto st = [&]() {
#pragma unroll
        for (int it = 0; it < 4; ++it) {
            int id = t + it*256; int row = id >> 3, c4 = id & 7;
            Xs[(c4*4+0)*132 + row] = xr[it].x;
            Xs[(c4*4+1)*132 + row] = xr[it].y;
            Xs[(c4*4+2)*132 + row] = xr[it].z;
            Xs[(c4*4+3)*132 + row] = xr[it].w;
        }
#pragma unroll
        for (int it = 0; it < 2; ++it) {
            int id = t + it*256; int row = id >> 4, c4 = id & 15;
            *(float4*)&Ws[row*64 + c4*4] = wr[it];
        }
    };

    ld(0); st(); __syncthreads();
    for (int kt = 0; kt < 32; ++kt) {
        if (kt < 31) ld(kt+1);
#pragma unroll 8
        for (int kk = 0; kk < 32; ++kk) {
            float4 a0 = *(float4*)&Xs[kk*132 + ty*8];
            float4 a1 = *(float4*)&Xs[kk*132 + ty*8 + 4];
            float4 bw = *(float4*)&Ws[kk*64 + tx*4];
            float a[8] = {a0.x,a0.y,a0.z,a0.w,a1.x,a1.y,a1.z,a1.w};
            float bvv[4] = {bw.x,bw.y,bw.z,bw.w};
#pragma unroll
            for (int i = 0; i < 8; ++i)
#pragma unroll
                for (int j = 0; j < 4; ++j) acc[i][j] += a[i]*bvv[j];
        }
        __syncthreads();
        if (kt < 31) { st(); __syncthreads(); }
    }

    float4 bo = *(const float4*)&bias[tx*4];
#pragma unroll
    for (int i = 0; i < 8; ++i) {
        float4 r;
        r.x = acc[i][0] + bo.x; r.y = acc[i][1] + bo.y;
        r.z = acc[i][2] + bo.z; r.w = acc[i][3] + bo.w;
        *(float4*)&O[(size_t)(m0 + ty*8 + i)*DD + tx*4] = r;
    }
}

// ---------------------------------------------------------------------------
// Gram partials: per (batch, chunk of 128 keys): partial G = K^T K and Ksum
// ---------------------------------------------------------------------------
__global__ __launch_bounds__(256) void k_gram() {
    const int b = blockIdx.y, c = blockIdx.x;
    __shared__ float Ks2[128*65];
    const int t = threadIdx.x;
    const float* kp = g_kp + (size_t)(b*SS + c*128)*DD;

    for (int id = t; id < 128*16; id += 256) {
        int row = id >> 4, c4 = id & 15;
        float4 v = *(const float4*)&kp[row*DD + c4*4];
        Ks2[row*65 + c4*4+0] = v.x; Ks2[row*65 + c4*4+1] = v.y;
        Ks2[row*65 + c4*4+2] = v.z; Ks2[row*65 + c4*4+3] = v.w;
    }
    __syncthreads();

    int a = t >> 2, b0 = (t & 3) * 16;
    float acc[16];
#pragma unroll
    for (int i = 0; i < 16; ++i) acc[i] = 0.f;
    for (int j = 0; j < 128; ++j) {
        float ka = Ks2[j*65 + a];
#pragma unroll
        for (int bb = 0; bb < 16; ++bb) acc[bb] += ka * Ks2[j*65 + b0 + bb];
    }
    float* gp = g_Gpart + (size_t)(b*16 + c)*4096;
#pragma unroll
    for (int bb = 0; bb < 16; ++bb) gp[a*64 + b0 + bb] = acc[bb];

    if (t < 64) {
        float s = 0.f;
        for (int j = 0; j < 128; ++j) s += Ks2[j*65 + t];
        g_Kspart[(b*16 + c)*64 + t] = s;
    }
}

__global__ void k_gramred() {
    int idx = blockIdx.x * 256 + threadIdx.x;
    if (idx < BB*4096) {
        int b = idx >> 12, e = idx & 4095;
        float s = 0.f;
#pragma unroll
        for (int c = 0; c < 16; ++c) s += g_Gpart[(size_t)(b*16+c)*4096 + e];
        g_G[idx] = s;
    } else if (idx < BB*4096 + BB*64) {
        int r = idx - BB*4096; int b = r >> 6, e = r & 63;
        float s = 0.f;
#pragma unroll
        for (int c = 0; c < 16; ++c) s += g_Kspart[(b*16+c)*64 + e];
        g_Ksum[r] = s;
    }
}

// ---------------------------------------------------------------------------
// Fused attention + output GEMM.
// Grid (32 q-blocks, 4 batches), 256 threads, 64 queries per CTA.
// Row stats from Gram matrix; single flash pass; epilogue head @ W_eff + bout.
// ---------------------------------------------------------------------------
#define AST 68
#define ATTN_SMEM_BYTES ((4*64*AST + 64*17 + 4*64) * 4)

__global__ __launch_bounds__(256) void k_attn(const float* __restrict__ bout,
                                              float* __restrict__ out)
{
    extern __shared__ float sm[];
    float* qs = sm;               // [d][q]
    float* Ks = qs + 64*AST;      // [d][k]  -> reused as hs [d][q]
    float* Vs = Ks + 64*AST;      // [k][d]  -> reused as ws [d][n]
    float* Ps = Vs + 64*AST;      // [k][q]  ; prologue: G [a][.]
    float* red  = Ps + 64*AST;    // [64][17]
    float* c0   = red + 64*17;
    float* c1   = c0 + 64;
    float* linv = c1 + 64;
    float* ksm  = linv + 64;

    const int t = threadIdx.x;
    const int b = blockIdx.y;
    const int qbase = blockIdx.x * 64;

    // --- load q block (transposed) + G + Ksum ---
    const float* qp = g_qp + (size_t)(b*SS + qbase)*DD;
    for (int id = t; id < 1024; id += 256) {
        int q = id >> 4, c4 = id & 15;
        float4 v = *(const float4*)&qp[q*DD + c4*4];
        qs[(c4*4+0)*AST + q] = v.x; qs[(c4*4+1)*AST + q] = v.y;
        qs[(c4*4+2)*AST + q] = v.z; qs[(c4*4+3)*AST + q] = v.w;
    }
    const float* Gp = g_G + (size_t)b*4096;
    for (int id = t; id < 1024; id += 256) {
        int a = id >> 4, c4 = id & 15;
        *(float4*)&Ps[a*AST + c4*4] = *(const float4*)&Gp[a*64 + c4*4];
    }
    if (t < 64) ksm[t] = g_Ksum[b*64 + t];
    __syncthreads();

    // --- per-query layernorm stats: mu = q.Ksum/(32*S), sum s^2 = qGq/1024 ---
    {
        int q = t >> 2, b0 = (t & 3) * 16;
        float qb[16];
#pragma unroll
        for (int ii = 0; ii < 16; ++ii) qb[ii] = qs[(b0+ii)*AST + q];
        float su = 0.f;
#pragma unroll
        for (int ii = 0; ii < 16; ++ii) su += qb[ii] * ksm[b0+ii];
        float sq = 0.f;
        for (int a = 0; a < 64; ++a) {
            float qa = qs[a*AST + q];
            float ta = 0.f;
#pragma unroll
            for (int ii = 0; ii < 16; ++ii) ta += Ps[a*AST + b0 + ii] * qb[ii];
            sq += qa * ta;
        }
        su += __shfl_xor_sync(0xffffffffu, su, 1);
        su += __shfl_xor_sync(0xffffffffu, su, 2);
        sq += __shfl_xor_sync(0xffffffffu, sq, 1);
        sq += __shfl_xor_sync(0xffffffffu, sq, 2);
        float mu  = su * (1.f/(32.f*(float)SS));
        float var = (sq*(1.f/1024.f) - (float)SS*mu*mu) * (1.f/((float)SS - 1.f));
        float rinv = 1.f / (sqrtf(var) + 1e-8f);
        c1[q] = rinv * (1.f/32.f);
        c0[q] = -mu * rinv;
    }
    __syncthreads();

    const int ty = t >> 4, tx = t & 15;
    float rc0[4], rc1[4];
#pragma unroll
    for (int i = 0; i < 4; ++i) { rc0[i] = c0[ty*4+i]; rc1[i] = c1[ty*4+i]; }

    float acc_o[4][4];
#pragma unroll
    for (int i = 0; i < 4; ++i)
#pragma unroll
        for (int j = 0; j < 4; ++j) acc_o[i][j] = 0.f;
    float lacc[4] = {0.f, 0.f, 0.f, 0.f};

    const float* kpb = g_kp + (size_t)b*SS*DD;
    const float* vpb = g_vp + (size_t)b*SS*DD;

    // --- flash loop over 32 key chunks of 64 ---
    for (int kc = 0; kc < 32; ++kc) {
        __syncthreads();
        const float* kcp = kpb + kc*64*DD;
        const float* vcp = vpb + kc*64*DD;
        for (int id = t; id < 1024; id += 256) {
            int k = id >> 4, c4 = id & 15;
            float4 kv = *(const float4*)&kcp[k*DD + c4*4];
            Ks[(c4*4+0)*AST + k] = kv.x; Ks[(c4*4+1)*AST + k] = kv.y;
            Ks[(c4*4+2)*AST + k] = kv.z; Ks[(c4*4+3)*AST + k] = kv.w;
            *(float4*)&Vs[k*AST + c4*4] = *(const float4*)&vcp[k*DD + c4*4];
        }
        __syncthreads();

        // phase 1: S = q k^T, p = exp((s/32 - mu)/(sigma+eps))
        float dv[4][4];
#pragma unroll
        for (int i = 0; i < 4; ++i)
#pragma unroll
            for (int j = 0; j < 4; ++j) dv[i][j] = 0.f;
#pragma unroll 8
        for (int d = 0; d < 64; ++d) {
            float4 qv = *(float4*)&qs[d*AST + ty*4];
            float4 kv = *(float4*)&Ks[d*AST + tx*4];
            float qa[4] = {qv.x,qv.y,qv.z,qv.w};
            float ka[4] = {kv.x,kv.y,kv.z,kv.w};
#pragma unroll
            for (int i = 0; i < 4; ++i)
#pragma unroll
                for (int j = 0; j < 4; ++j) dv[i][j] += qa[i]*ka[j];
        }
#pragma unroll
        for (int i = 0; i < 4; ++i)
#pragma unroll
            for (int j = 0; j < 4; ++j) {
                float p = __expf(dv[i][j]*rc1[i] + rc0[i]);
                lacc[i] += p;
                Ps[(tx*4+j)*AST + ty*4+i] = p;
            }
        __syncthreads();

        // phase 2: O += P V
#pragma unroll 8
        for (int kk = 0; kk < 64; ++kk) {
            float4 pv = *(float4*)&Ps[kk*AST + ty*4];
            float4 vv = *(float4*)&Vs[kk*AST + tx*4];
            float pa[4] = {pv.x,pv.y,pv.z,pv.w};
            float va[4] = {vv.x,vv.y,vv.z,vv.w};
#pragma unroll
            for (int i = 0; i < 4; ++i)
#pragma unroll
                for (int j = 0; j < 4; ++j) acc_o[i][j] += pa[i]*va[j];
        }
    }

    // --- rowsum reduce, head = O/l ---
    __syncthreads();
#pragma unroll
    for (int i = 0; i < 4; ++i) red[(ty*4+i)*17 + tx] = lacc[i];
    __syncthreads();
    if (t < 64) {
        float s = 0.f;
#pragma unroll
        for (int x = 0; x < 16; ++x) s += red[t*17 + x];
        linv[t] = 1.f / s;
    }
    __syncthreads();
    float* hs = Ks;  // reuse
#pragma unroll
    for (int i = 0; i < 4; ++i) {
        float li = linv[ty*4+i];
#pragma unroll
        for (int j = 0; j < 4; ++j) hs[(tx*4+j)*AST + ty*4+i] = acc_o[i][j]*li;
    }
    __syncthreads();

    // --- epilogue: out = head @ W_eff + bout ---
    float* ws = Vs;  // reuse
    float* orow = out + (size_t)(b*SS + qbase)*HH;
    for (int nc = 0; nc < 16; ++nc) {
        for (int id = t; id < 1024; id += 256) {
            int dd = id >> 4, c4 = id & 15;
            *(float4*)&ws[dd*AST + c4*4] =
                *(const float4*)&g_Weff[dd*HH + nc*64 + c4*4];
        }
        __syncthreads();
        float acc[4][4];
#pragma unroll
        for (int i = 0; i < 4; ++i)
#pragma unroll
            for (int j = 0; j < 4; ++j) acc[i][j] = 0.f;
#pragma unroll 8
        for (int d = 0; d < 64; ++d) {
            float4 hv = *(float4*)&hs[d*AST + ty*4];
            float4 wv = *(float4*)&ws[d*AST + tx*4];
            float ha[4] = {hv.x,hv.y,hv.z,hv.w};
            float wa[4] = {wv.x,wv.y,wv.z,wv.w};
#pragma unroll
            for (int i = 0; i < 4; ++i)
#pragma unroll
                for (int j = 0; j < 4; ++j) acc[i][j] += ha[i]*wa[j];
        }
        float4 bo = *(const float4*)&bout[nc*64 + tx*4];
#pragma unroll
        for (int i = 0; i < 4; ++i) {
            float4 r;
            r.x = acc[i][0] + bo.x; r.y = acc[i][1] + bo.y;
            r.z = acc[i][2] + bo.z; r.w = acc[i][3] + bo.w;
            *(float4*)&orow[(size_t)(ty*4+i)*HH + nc*64 + tx*4] = r;
        }
        __syncthreads();
    }
}

// ---------------------------------------------------------------------------
extern "C" void kernel_launch(void* const* d_in, const int* in_sizes, int n_in,
                              void* d_out, int out_size)
{
    const float* query = (const float*)d_in[0];
    const float* key   = (const float*)d_in[1];
    const float* value = (const float*)d_in[2];
    // d_in[3] = mask (provably no-op), d_in[12] = seq_mask (0)
    const float* Wq   = (const float*)d_in[4];
    const float* bq   = (const float*)d_in[5];
    const float* Wk   = (const float*)d_in[6];
    const float* bk   = (const float*)d_in[7];
    const float* Wv   = (const float*)d_in[8];
    const float* bv   = (const float*)d_in[9];
    const float* Wout = (const float*)d_in[10];
    const float* bo   = (const float*)d_in[11];
    float* out = (float*)d_out;

    cudaFuncSetAttribute(k_attn, cudaFuncAttributeMaxDynamicSharedMemorySize,
                         ATTN_SMEM_BYTES);

    k_weff<<<256, 256>>>(Wout);
    k_proj<<<dim3(64, 3), 256>>>(query, key, value, Wq, bq, Wk, bk, Wv, bv);
    k_gram<<<dim3(16, BB), 256>>>();
    k_gramred<<<66, 256>>>();
    k_attn<<<dim3(32, BB), 256, ATTN_SMEM_BYTES>>>(bo, out);
}

// round 2
// speedup vs baseline: 1.5550x; 1.5550x over previous
#include <cuda_runtime.h>
#include <math.h>

// Problem constants
#define BB 4
#define SS 2048
#define HH 1024
#define DD 64
#define MM (BB*SS)   // 8192

// Scratch (device globals; no allocation allowed)
__device__ float g_qp[MM*DD];
__device__ float g_kp[MM*DD];
__device__ float g_vp[MM*DD];
__device__ float g_Gpart[BB*16*DD*DD];
__device__ float g_Kspart[BB*16*DD];
__device__ float g_G[BB*DD*DD];
__device__ float g_Ksum[BB*DD];
__device__ float g_Weff[DD*HH];

// ---------------------------------------------------------------------------
// W_eff[d][j] = sum_h Wout[h*64+d][j]   (heads share weights -> fold tile())
// ---------------------------------------------------------------------------
__global__ void k_weff(const float* __restrict__ Wout) {
    int idx = blockIdx.x * 256 + threadIdx.x;   // 65536 total
    int d = idx >> 10, j = idx & 1023;
    float s = 0.f;
#pragma unroll
    for (int h = 0; h < 16; ++h) s += Wout[(h*DD + d)*HH + j];
    g_Weff[idx] = s;
    (void)d;
}

// ---------------------------------------------------------------------------
// Projection GEMM: out[8192,64] = X[8192,1024] @ W[1024,64] + bias
// blockIdx.y selects q/k/v.  BM=128, BN=64, BK=32, 256 threads, 8x4 microtile.
// ---------------------------------------------------------------------------
__global__ __launch_bounds__(256) void k_proj(
    const float* __restrict__ Xq, const float* __restrict__ Xk, const float* __restrict__ Xv,
    const float* __restrict__ Wq, const float* __restrict__ bq,
    const float* __restrict__ Wk, const float* __restrict__ bk,
    const float* __restrict__ Wv, const float* __restrict__ bv)
{
    const float* X; const float* W; const float* bias; float* O;
    if (blockIdx.y == 0)      { X = Xq; W = Wq; bias = bq; O = g_qp; }
    else if (blockIdx.y == 1) { X = Xk; W = Wk; bias = bk; O = g_kp; }
    else                      { X = Xv; W = Wv; bias = bv; O = g_vp; }

    __shared__ float Xs[32*132];   // [k][m], padded
    __shared__ float Ws[32*64];    // [k][n]

    const int t  = threadIdx.x;
    const int m0 = blockIdx.x * 128;
    const int ty = t >> 4, tx = t & 15;

    float acc[8][4];
#pragma unroll
    for (int i = 0; i < 8; ++i)
#pragma unroll
        for (int j = 0; j < 4; ++j) acc[i][j] = 0.f;

    float4 xr[4]; float4 wr[2];

    auto ld = [&](int kt) {
        int k0 = kt * 32;
#pragma unroll
        for (int it = 0; it < 4; ++it) {
            int id = t + it*256; int row = id >> 3, c4 = id & 7;
            xr[it] = *(const float4*)&X[(size_t)(m0+row)*HH + k0 + c4*4];
        }
#pragma unroll
        for (int it = 0; it < 2; ++it) {
            int id = t + it*256; int row = id >> 4, c4 = id & 15;
            wr[it] = *(const float4*)&W[(size_t)(k0+row)*DD + c4*4];
        }
    };
    auto st = [&]() {
#pragma unroll
        for (int it = 0; it < 4; ++it) {
            int id = t + it*256; int row = id >> 3, c4 = id & 7;
            Xs[(c4*4+0)*132 + row] = xr[it].x;
            Xs[(c4*4+1)*132 + row] = xr[it].y;
            Xs[(c4*4+2)*132 + row] = xr[it].z;
            Xs[(c4*4+3)*132 + row] = xr[it].w;
        }
#pragma unroll
        for (int it = 0; it < 2; ++it) {
            int id = t + it*256; int row = id >> 4, c4 = id & 15;
            *(float4*)&Ws[row*64 + c4*4] = wr[it];
        }
    };

    ld(0); st(); __syncthreads();
    for (int kt = 0; kt < 32; ++kt) {
        if (kt < 31) ld(kt+1);
#pragma unroll 8
        for (int kk = 0; kk < 32; ++kk) {
            float4 a0 = *(float4*)&Xs[kk*132 + ty*8];
            float4 a1 = *(float4*)&Xs[kk*132 + ty*8 + 4];
            float4 bw = *(float4*)&Ws[kk*64 + tx*4];
            float a[8] = {a0.x,a0.y,a0.z,a0.w,a1.x,a1.y,a1.z,a1.w};
            float bvv[4] = {bw.x,bw.y,bw.z,bw.w};
#pragma unroll
            for (int i = 0; i < 8; ++i)
#pragma unroll
                for (int j = 0; j < 4; ++j) acc[i][j] += a[i]*bvv[j];
        }
        __syncthreads();
        if (kt < 31) { st(); __syncthreads(); }
    }

    float4 bo = *(const float4*)&bias[tx*4];
#pragma unroll
    for (int i = 0; i < 8; ++i) {
        float4 r;
        r.x = acc[i][0] + bo.x; r.y = acc[i][1] + bo.y;
        r.z = acc[i][2] + bo.z; r.w = acc[i][3] + bo.w;
        *(float4*)&O[(size_t)(m0 + ty*8 + i)*DD + tx*4] = r;
    }
}

// ---------------------------------------------------------------------------
// Gram partials: per (batch, chunk of 128 keys): partial G = K^T K and Ksum
// ---------------------------------------------------------------------------
__global__ __launch_bounds__(256) void k_gram() {
    const int b = blockIdx.y, c = blockIdx.x;
    __shared__ float Ks2[128*65];
    const int t = threadIdx.x;
    const float* kp = g_kp + (size_t)(b*SS + c*128)*DD;

    for (int id = t; id < 128*16; id += 256) {
        int row = id >> 4, c4 = id & 15;
        float4 v = *(const float4*)&kp[row*DD + c4*4];
        Ks2[row*65 + c4*4+0] = v.x; Ks2[row*65 + c4*4+1] = v.y;
        Ks2[row*65 + c4*4+2] = v.z; Ks2[row*65 + c4*4+3] = v.w;
    }
    __syncthreads();

    int a = t >> 2, b0 = (t & 3) * 16;
    float acc[16];
#pragma unroll
    for (int i = 0; i < 16; ++i) acc[i] = 0.f;
    for (int j = 0; j < 128; ++j) {
        float ka = Ks2[j*65 + a];
#pragma unroll
        for (int bb = 0; bb < 16; ++bb) acc[bb] += ka * Ks2[j*65 + b0 + bb];
    }
    float* gp = g_Gpart + (size_t)(b*16 + c)*4096;
#pragma unroll
    for (int bb = 0; bb < 16; ++bb) gp[a*64 + b0 + bb] = acc[bb];

    if (t < 64) {
        float s = 0.f;
        for (int j = 0; j < 128; ++j) s += Ks2[j*65 + t];
        g_Kspart[(b*16 + c)*64 + t] = s;
    }
}

__global__ void k_gramred() {
    int idx = blockIdx.x * 256 + threadIdx.x;
    if (idx < BB*4096) {
        int b = idx >> 12, e = idx & 4095;
        float s = 0.f;
#pragma unroll
        for (int c = 0; c < 16; ++c) s += g_Gpart[(size_t)(b*16+c)*4096 + e];
        g_G[idx] = s;
    } else if (idx < BB*4096 + BB*64) {
        int r = idx - BB*4096; int b = r >> 6, e = r & 63;
        float s = 0.f;
#pragma unroll
        for (int c = 0; c < 16; ++c) s += g_Kspart[(b*16+c)*64 + e];
        g_Ksum[r] = s;
    }
}

// ---------------------------------------------------------------------------
// Fused attention + output GEMM.
// Grid (32 q-blocks, 4 batches), 256 threads, 64 queries per CTA.
// Row stats from Gram matrix; single flash pass; epilogue head @ W_eff + bout.
// ---------------------------------------------------------------------------
#define AST 68
#define ATTN_SMEM_BYTES ((4*64*AST + 64*17 + 4*64) * 4)

__global__ __launch_bounds__(256) void k_attn(const float* __restrict__ bout,
                                              float* __restrict__ out)
{
    extern __shared__ float sm[];
    float* qs = sm;               // [d][q]
    float* Ks = qs + 64*AST;      // [d][k]  -> reused as hs [d][q]
    float* Vs = Ks + 64*AST;      // [k][d]  -> reused as ws [d][n]
    float* Ps = Vs + 64*AST;      // [k][q]  ; prologue: G [a][.]
    float* red  = Ps + 64*AST;    // [64][17]
    float* c0   = red + 64*17;
    float* c1   = c0 + 64;
    float* linv = c1 + 64;
    float* ksm  = linv + 64;

    const int t = threadIdx.x;
    const int b = blockIdx.y;
    const int qbase = blockIdx.x * 64;

    // --- load q block (transposed) + G + Ksum ---
    const float* qp = g_qp + (size_t)(b*SS + qbase)*DD;
    for (int id = t; id < 1024; id += 256) {
        int q = id >> 4, c4 = id & 15;
        float4 v = *(const float4*)&qp[q*DD + c4*4];
        qs[(c4*4+0)*AST + q] = v.x; qs[(c4*4+1)*AST + q] = v.y;
        qs[(c4*4+2)*AST + q] = v.z; qs[(c4*4+3)*AST + q] = v.w;
    }
    const float* Gp = g_G + (size_t)b*4096;
    for (int id = t; id < 1024; id += 256) {
        int a = id >> 4, c4 = id & 15;
        *(float4*)&Ps[a*AST + c4*4] = *(const float4*)&Gp[a*64 + c4*4];
    }
    if (t < 64) ksm[t] = g_Ksum[b*64 + t];
    __syncthreads();

    // --- per-query layernorm stats: mu = q.Ksum/(32*S), sum s^2 = qGq/1024 ---
    {
        int q = t >> 2, b0 = (t & 3) * 16;
        float qb[16];
#pragma unroll
        for (int ii = 0; ii < 16; ++ii) qb[ii] = qs[(b0+ii)*AST + q];
        float su = 0.f;
#pragma unroll
        for (int ii = 0; ii < 16; ++ii) su += qb[ii] * ksm[b0+ii];
        float sq = 0.f;
        for (int a = 0; a < 64; ++a) {
            float qa = qs[a*AST + q];
            float ta = 0.f;
#pragma unroll
            for (int ii = 0; ii < 16; ++ii) ta += Ps[a*AST + b0 + ii] * qb[ii];
            sq += qa * ta;
        }
        su += __shfl_xor_sync(0xffffffffu, su, 1);
        su += __shfl_xor_sync(0xffffffffu, su, 2);
        sq += __shfl_xor_sync(0xffffffffu, sq, 1);
        sq += __shfl_xor_sync(0xffffffffu, sq, 2);
        float mu  = su * (1.f/(32.f*(float)SS));
        float var = (sq*(1.f/1024.f) - (float)SS*mu*mu) * (1.f/((float)SS - 1.f));
        float rinv = 1.f / (sqrtf(var) + 1e-8f);
        c1[q] = rinv * (1.f/32.f);
        c0[q] = -mu * rinv;
    }
    __syncthreads();

    const int ty = t >> 4, tx = t & 15;
    float rc0[4], rc1[4];
#pragma unroll
    for (int i = 0; i < 4; ++i) { rc0[i] = c0[ty*4+i]; rc1[i] = c1[ty*4+i]; }

    float acc_o[4][4];
#pragma unroll
    for (int i = 0; i < 4; ++i)
#pragma unroll
        for (int j = 0; j < 4; ++j) acc_o[i][j] = 0.f;
    float lacc[4] = {0.f, 0.f, 0.f, 0.f};

    const float* kpb = g_kp + (size_t)b*SS*DD;
    const float* vpb = g_vp + (size_t)b*SS*DD;

    // --- flash loop over 32 key chunks of 64 ---
    for (int kc = 0; kc < 32; ++kc) {
        __syncthreads();
        const float* kcp = kpb + kc*64*DD;
        const float* vcp = vpb + kc*64*DD;
        for (int id = t; id < 1024; id += 256) {
            int k = id >> 4, c4 = id & 15;
            float4 kv = *(const float4*)&kcp[k*DD + c4*4];
            Ks[(c4*4+0)*AST + k] = kv.x; Ks[(c4*4+1)*AST + k] = kv.y;
            Ks[(c4*4+2)*AST + k] = kv.z; Ks[(c4*4+3)*AST + k] = kv.w;
            *(float4*)&Vs[k*AST + c4*4] = *(const float4*)&vcp[k*DD + c4*4];
        }
        __syncthreads();

        // phase 1: S = q k^T, p = exp((s/32 - mu)/(sigma+eps))
        float dv[4][4];
#pragma unroll
        for (int i = 0; i < 4; ++i)
#pragma unroll
            for (int j = 0; j < 4; ++j) dv[i][j] = 0.f;
#pragma unroll 8
        for (int d = 0; d < 64; ++d) {
            float4 qv = *(float4*)&qs[d*AST + ty*4];
            float4 kv = *(float4*)&Ks[d*AST + tx*4];
            float qa[4] = {qv.x,qv.y,qv.z,qv.w};
            float ka[4] = {kv.x,kv.y,kv.z,kv.w};
#pragma unroll
            for (int i = 0; i < 4; ++i)
#pragma unroll
                for (int j = 0; j < 4; ++j) dv[i][j] += qa[i]*ka[j];
        }
#pragma unroll
        for (int i = 0; i < 4; ++i)
#pragma unroll
            for (int j = 0; j < 4; ++j) {
                float p = __expf(dv[i][j]*rc1[i] + rc0[i]);
                lacc[i] += p;
                Ps[(tx*4+j)*AST + ty*4+i] = p;
            }
        __syncthreads();

        // phase 2: O += P V
#pragma unroll 8
        for (int kk = 0; kk < 64; ++kk) {
            float4 pv = *(float4*)&Ps[kk*AST + ty*4];
            float4 vv = *(float4*)&Vs[kk*AST + tx*4];
            float pa[4] = {pv.x,pv.y,pv.z,pv.w};
            float va[4] = {vv.x,vv.y,vv.z,vv.w};
#pragma unroll
            for (int i = 0; i < 4; ++i)
#pragma unroll
                for (int j = 0; j < 4; ++j) acc_o[i][j] += pa[i]*va[j];
        }
    }

    // --- rowsum reduce, head = O/l ---
    __syncthreads();
#pragma unroll
    for (int i = 0; i < 4; ++i) red[(ty*4+i)*17 + tx] = lacc[i];
    __syncthreads();
    if (t < 64) {
        float s = 0.f;
#pragma unroll
        for (int x = 0; x < 16; ++x) s += red[t*17 + x];
        linv[t] = 1.f / s;
    }
    __syncthreads();
    float* hs = Ks;  // reuse
#pragma unroll
    for (int i = 0; i < 4; ++i) {
        float li = linv[ty*4+i];
#pragma unroll
        for (int j = 0; j < 4; ++j) hs[(tx*4+j)*AST + ty*4+i] = acc_o[i][j]*li;
    }
    __syncthreads();

    // --- epilogue: out = head @ W_eff + bout ---
    float* ws = Vs;  // reuse
    float* orow = out + (size_t)(b*SS + qbase)*HH;
    for (int nc = 0; nc < 16; ++nc) {
        for (int id = t; id < 1024; id += 256) {
            int dd = id >> 4, c4 = id & 15;
            *(float4*)&ws[dd*AST + c4*4] =
                *(const float4*)&g_Weff[dd*HH + nc*64 + c4*4];
        }
        __syncthreads();
        float acc[4][4];
#pragma unroll
        for (int i = 0; i < 4; ++i)
#pragma unroll
            for (int j = 0; j < 4; ++j) acc[i][j] = 0.f;
#pragma unroll 8
        for (int d = 0; d < 64; ++d) {
            float4 hv = *(float4*)&hs[d*AST + ty*4];
            float4 wv = *(float4*)&ws[d*AST + tx*4];
            float ha[4] = {hv.x,hv.y,hv.z,hv.w};
            float wa[4] = {wv.x,wv.y,wv.z,wv.w};
#pragma unroll
            for (int i = 0; i < 4; ++i)
#pragma unroll
                for (int j = 0; j < 4; ++j) acc[i][j] += ha[i]*wa[j];
        }
        float4 bo = *(const float4*)&bout[nc*64 + tx*4];
#pragma unroll
        for (int i = 0; i < 4; ++i) {
            float4 r;
            r.x = acc[i][0] + bo.x; r.y = acc[i][1] + bo.y;
            r.z = acc[i][2] + bo.z; r.w = acc[i][3] + bo.w;
            *(float4*)&orow[(size_t)(ty*4+i)*HH + nc*64 + tx*4] = r;
        }
        __syncthreads();
    }
}

// ---------------------------------------------------------------------------
extern "C" void kernel_launch(void* const* d_in, const int* in_sizes, int n_in,
                              void* d_out, int out_size)
{
    const float* query = (const float*)d_in[0];
    const float* key   = (const float*)d_in[1];
    const float* value = (const float*)d_in[2];
    // d_in[3] = mask (provably no-op), d_in[12] = seq_mask (0)
    const float* Wq   = (const float*)d_in[4];
    const float* bq   = (const float*)d_in[5];
    const float* Wk   = (const float*)d_in[6];
    const float* bk   = (const float*)d_in[7];
    const float* Wv   = (const float*)d_in[8];
    const float* bv   = (const float*)d_in[9];
    const float* Wout = (const float*)d_in[10];
    const float* bo   = (const float*)d_in[11];
    float* out = (float*)d_out;

    cudaFuncSetAttribute(k_attn, cudaFuncAttributeMaxDynamicSharedMemorySize,
                         ATTN_SMEM_BYTES);

    k_weff<<<256, 256>>>(Wout);
    k_proj<<<dim3(64, 3), 256>>>(query, key, value, Wq, bq, Wk, bk, Wv, bv);
    k_gram<<<dim3(16, BB), 256>>>();
    k_gramred<<<66, 256>>>();
    k_attn<<<dim3(32, BB), 256, ATTN_SMEM_BYTES>>>(bo, out);
}

// round 4
// speedup vs baseline: 3.4223x; 2.2008x over previous
#include <cuda_runtime.h>
#include <cuda_fp16.h>
#include <cstdint>
#include <math.h>

#define BB 4
#define SQ 2048
#define HH 1024
#define DD 64
#define MT (BB*SQ)   // 8192

// ---------------- scratch ----------------
__device__ __align__(16) float g_qp[MT*DD];
__device__ __align__(16) float g_kp[MT*DD];
__device__ __align__(16) __half g_qh[MT*DD], g_ql[MT*DD];
__device__ __align__(16) __half g_kh[MT*DD], g_kl[MT*DD];
__device__ __align__(16) __half g_vh[MT*DD], g_vl[MT*DD];
__device__ __align__(16) __half g_WTh[3*DD*HH], g_WTl[3*DD*HH];   // [sel][n=64][k=1024]
__device__ __align__(16) __half g_WeffTh[HH*DD], g_WeffTl[HH*DD]; // [j=1024][d=64]
__device__ float g_Gpart[BB*16*DD*DD];
__device__ float g_Kspart[BB*16*DD];
__device__ float g_G[BB*DD*DD];
__device__ float g_Ksum[BB*DD];
__device__ float g_c0[MT], g_c1[MT];

// ---------------- helpers ----------------
__device__ __forceinline__ uint32_t su32(const void* p){
    uint32_t a;
    asm("{ .reg .u64 t; cvta.to.shared.u64 t, %1; cvt.u32.u64 %0, t; }" : "=r"(a) : "l"(p));
    return a;
}
__device__ __forceinline__ void ldsm4(uint32_t& r0,uint32_t& r1,uint32_t& r2,uint32_t& r3,uint32_t a){
    asm volatile("ldmatrix.sync.aligned.m8n8.x4.shared.b16 {%0,%1,%2,%3}, [%4];"
                 : "=r"(r0),"=r"(r1),"=r"(r2),"=r"(r3) : "r"(a));
}
__device__ __forceinline__ void ldsm2(uint32_t& r0,uint32_t& r1,uint32_t a){
    asm volatile("ldmatrix.sync.aligned.m8n8.x2.shared.b16 {%0,%1}, [%2];"
                 : "=r"(r0),"=r"(r1) : "r"(a));
}
__device__ __forceinline__ void ldsm2t(uint32_t& r0,uint32_t& r1,uint32_t a){
    asm volatile("ldmatrix.sync.aligned.m8n8.x2.trans.shared.b16 {%0,%1}, [%2];"
                 : "=r"(r0),"=r"(r1) : "r"(a));
}
__device__ __forceinline__ void mma16816(float* c, const uint32_t* a, uint32_t b0, uint32_t b1){
    asm volatile("mma.sync.aligned.m16n8k16.row.col.f32.f16.f16.f32 "
                 "{%0,%1,%2,%3}, {%4,%5,%6,%7}, {%8,%9}, {%0,%1,%2,%3};"
                 : "+f"(c[0]),"+f"(c[1]),"+f"(c[2]),"+f"(c[3])
                 : "r"(a[0]),"r"(a[1]),"r"(a[2]),"r"(a[3]), "r"(b0),"r"(b1));
}
#define CPA(dst,src) asm volatile("cp.async.cg.shared.global [%0], [%1], 16;" :: "r"(dst),"l"(src))
#define CPC() asm volatile("cp.async.commit_group;" ::: "memory")
#define CPW(n) asm volatile("cp.async.wait_group %0;" :: "n"(n) : "memory")

__device__ __forceinline__ void split_pair(float x, float y, uint32_t& hi, uint32_t& lo){
    __half2 h = __floats2half2_rn(x,y);
    float2 f = __half22float2(h);
    __half2 l = __floats2half2_rn(x - f.x, y - f.y);
    hi = *(uint32_t*)&h; lo = *(uint32_t*)&l;
}

// ---------------- prep: hi/lo W^T + folded Weff^T ----------------
__global__ void k_prep(const float* __restrict__ Wq, const float* __restrict__ Wk,
                       const float* __restrict__ Wv, const float* __restrict__ Wout){
    int idx = blockIdx.x*256 + threadIdx.x;   // 262144
    if (idx < 3*65536) {
        int w = idx >> 16, r = idx & 65535, n = r >> 10, k = r & 1023;
        const float* W = w==0 ? Wq : (w==1 ? Wk : Wv);
        float x = W[k*DD + n];
        __half h = __float2half(x);
        g_WTh[idx] = h;
        g_WTl[idx] = __float2half(x - __half2float(h));
    } else {
        int r = idx - 3*65536, j = r >> 6, d = r & 63;
        float s = 0.f;
#pragma unroll
        for (int h = 0; h < 16; ++h) s += Wout[(h*DD + d)*HH + j];
        __half hh = __float2half(s);
        g_WeffTh[j*DD + d] = hh;
        g_WeffTl[j*DD + d] = __float2half(s - __half2float(hh));
    }
}

// ---------------- projection via mma: X[8192,1024]@W[1024,64]+b ----------------
#define PP 40   // pitch in halves (80 B)
__global__ __launch_bounds__(256) void k_proj_mma(
    const float* __restrict__ Xq, const float* __restrict__ Xk, const float* __restrict__ Xv,
    const float* __restrict__ bq, const float* __restrict__ bk, const float* __restrict__ bv)
{
    __shared__ __align__(16) __half Xh[128*PP], Xl[128*PP];
    __shared__ __align__(16) __half Wh[64*PP],  Wl[64*PP];

    const int t = threadIdx.x, w = t>>5, lane = t&31;
    const int sel = blockIdx.y, m0 = blockIdx.x*128;
    const int wm = w&3, wn = w>>2;
    const float* X    = sel==0?Xq:(sel==1?Xk:Xv);
    const float* bias = sel==0?bq:(sel==1?bk:bv);
    const __half* WTh = g_WTh + sel*65536;
    const __half* WTl = g_WTl + sel*65536;

    const int i8 = lane&7, q4 = lane>>3;
    const int mrow = i8 + ((q4&1)<<3), kcol = (q4>>1)<<3;
    const int s2 = (lane>>3)&1;
    const uint32_t xh_b = su32(Xh), xl_b = su32(Xl), wh_b = su32(Wh), wl_b = su32(Wl);

    float acc[2][4][4];
#pragma unroll
    for (int a=0;a<2;++a)
#pragma unroll
        for (int bq_=0;bq_<4;++bq_)
#pragma unroll
            for (int cq=0;cq<4;++cq) acc[a][bq_][cq]=0.f;

    float4 xr[4]; uint4 whr, wlr;
    auto LD = [&](int c){
        int k0 = c*32;
#pragma unroll
        for (int i=0;i<4;++i){ int id=t+i*256, row=id>>3, c4=id&7;
            xr[i] = *(const float4*)&X[(size_t)(m0+row)*HH + k0 + c4*4]; }
        { int row = t>>2, cc = t&3;
          whr = *(const uint4*)(WTh + (size_t)row*HH + k0 + cc*8);
          wlr = *(const uint4*)(WTl + (size_t)row*HH + k0 + cc*8); }
    };
    auto ST = [&](){
#pragma unroll
        for (int i=0;i<4;++i){ int id=t+i*256, row=id>>3, c4=id&7;
            uint32_t h0,l0,h1,l1;
            split_pair(xr[i].x, xr[i].y, h0, l0);
            split_pair(xr[i].z, xr[i].w, h1, l1);
            *(uint2*)&Xh[row*PP + c4*4] = make_uint2(h0,h1);
            *(uint2*)&Xl[row*PP + c4*4] = make_uint2(l0,l1); }
        { int row = t>>2, cc = t&3;
          *(uint4*)&Wh[row*PP + cc*8] = whr;
          *(uint4*)&Wl[row*PP + cc*8] = wlr; }
    };

    LD(0); ST(); __syncthreads();
    for (int c=0;c<32;++c){
        if (c<31) LD(c+1);
#pragma unroll
        for (int ks=0;ks<2;++ks){
            uint32_t ah[2][4], al[2][4];
#pragma unroll
            for (int mt=0;mt<2;++mt){
                uint32_t ra = (uint32_t)(((wm*32+mt*16+mrow)*PP + ks*16 + kcol)*2);
                ldsm4(ah[mt][0],ah[mt][1],ah[mt][2],ah[mt][3], xh_b + ra);
                ldsm4(al[mt][0],al[mt][1],al[mt][2],al[mt][3], xl_b + ra);
            }
#pragma unroll
            for (int nt=0;nt<4;++nt){
                uint32_t rb = (uint32_t)(((wn*32+nt*8+i8)*PP + ks*16 + s2*8)*2);
                uint32_t bh0,bh1,bl0,bl1;
                ldsm2(bh0,bh1, wh_b + rb);
                ldsm2(bl0,bl1, wl_b + rb);
#pragma unroll
                for (int mt=0;mt<2;++mt){
                    mma16816(acc[mt][nt], ah[mt], bh0, bh1);
                    mma16816(acc[mt][nt], ah[mt], bl0, bl1);
                    mma16816(acc[mt][nt], al[mt], bh0, bh1);
                }
            }
        }
        __syncthreads();
        if (c<31){ ST(); __syncthreads(); }
    }

    // epilogue
    const int g4 = lane>>2, tq = lane&3;
#pragma unroll
    for (int mt=0;mt<2;++mt)
#pragma unroll
    for (int nt=0;nt<4;++nt){
        int n = wn*32 + nt*8 + tq*2;
        float2 bb = __ldg((const float2*)&bias[n]);
#pragma unroll
        for (int hf=0;hf<2;++hf){
            int row = m0 + wm*32 + mt*16 + g4 + hf*8;
            float v0 = acc[mt][nt][hf*2+0] + bb.x;
            float v1 = acc[mt][nt][hf*2+1] + bb.y;
            size_t o = (size_t)row*DD + n;
            if (sel < 2){
                float* O = sel==0 ? g_qp : g_kp;
                *(float2*)&O[o] = make_float2(v0, v1);
            }
            uint32_t hi, lo;
            split_pair(v0, v1, hi, lo);
            __half* Oh = sel==0 ? g_qh : (sel==1 ? g_kh : g_vh);
            __half* Ol = sel==0 ? g_ql : (sel==1 ? g_kl : g_vl);
            *(uint32_t*)(Oh + o) = hi;
            *(uint32_t*)(Ol + o) = lo;
        }
    }
}

// ---------------- fp32 Gram + reduce (exact layernorm stats) ----------------
__global__ __launch_bounds__(256) void k_gram() {
    const int b = blockIdx.y, c = blockIdx.x;
    __shared__ float Ks2[128*65];
    const int t = threadIdx.x;
    const float* kp = g_kp + (size_t)(b*SQ + c*128)*DD;
    for (int id = t; id < 128*16; id += 256) {
        int row = id >> 4, c4 = id & 15;
        float4 v = *(const float4*)&kp[row*DD + c4*4];
        Ks2[row*65+c4*4+0]=v.x; Ks2[row*65+c4*4+1]=v.y;
        Ks2[row*65+c4*4+2]=v.z; Ks2[row*65+c4*4+3]=v.w;
    }
    __syncthreads();
    int a = t >> 2, b0 = (t & 3) * 16;
    float acc[16];
#pragma unroll
    for (int i = 0; i < 16; ++i) acc[i] = 0.f;
    for (int j = 0; j < 128; ++j) {
        float ka = Ks2[j*65 + a];
#pragma unroll
        for (int bb = 0; bb < 16; ++bb) acc[bb] += ka * Ks2[j*65 + b0 + bb];
    }
    float* gp = g_Gpart + (size_t)(b*16 + c)*4096;
#pragma unroll
    for (int bb = 0; bb < 16; ++bb) gp[a*64 + b0 + bb] = acc[bb];
    if (t < 64) {
        float s = 0.f;
        for (int j = 0; j < 128; ++j) s += Ks2[j*65 + t];
        g_Kspart[(b*16 + c)*64 + t] = s;
    }
}
__global__ void k_gramred() {
    int idx = blockIdx.x * 256 + threadIdx.x;
    if (idx < BB*4096) {
        int b = idx >> 12, e = idx & 4095;
        float s = 0.f;
#pragma unroll
        for (int c = 0; c < 16; ++c) s += g_Gpart[(size_t)(b*16+c)*4096 + e];
        g_G[idx] = s;
    } else if (idx < BB*4096 + BB*64) {
        int r = idx - BB*4096, b = r >> 6, e = r & 63;
        float s = 0.f;
#pragma unroll
        for (int c = 0; c < 16; ++c) s += g_Kspart[(b*16+c)*64 + e];
        g_Ksum[r] = s;
    }
}

// ---------------- per-query layernorm constants ----------------
#define STATS_SMEM ((4096 + 64 + 256*65)*4)
__global__ __launch_bounds__(256) void k_stats() {
    extern __shared__ float ss[];
    float* Gs = ss; float* Ks = Gs + 4096; float* qs = Ks + 64;
    const int t = threadIdx.x, b = blockIdx.y, q0 = blockIdx.x*256;
    for (int id = t; id < 4096; id += 256) Gs[id] = g_G[b*4096 + id];
    if (t < 64) Ks[t] = g_Ksum[b*64 + t];
    const float* qp = g_qp + (size_t)(b*SQ + q0)*DD;
    for (int id = t; id < 4096; id += 256) {
        int row = id >> 4, c4 = id & 15;
        float4 v = *(const float4*)&qp[row*DD + c4*4];
        qs[row*65+c4*4+0]=v.x; qs[row*65+c4*4+1]=v.y;
        qs[row*65+c4*4+2]=v.z; qs[row*65+c4*4+3]=v.w;
    }
    __syncthreads();
    float su = 0.f, sq = 0.f;
    for (int a = 0; a < 64; ++a) {
        float qa = qs[t*65 + a];
        su += qa * Ks[a];
        float ta = 0.f;
#pragma unroll 16
        for (int bb = 0; bb < 64; ++bb) ta += Gs[a*64 + bb] * qs[t*65 + bb];
        sq += qa * ta;
    }
    float mu  = su * (1.f/(32.f*(float)SQ));
    float var = (sq*(1.f/1024.f) - (float)SQ*mu*mu) * (1.f/((float)SQ - 1.f));
    float rinv = 1.f / (sqrtf(var) + 1e-8f);
    g_c1[b*SQ + q0 + t] = rinv * (1.f/32.f);
    g_c0[b*SQ + q0 + t] = -mu * rinv;
}

// ---------------- fused flash attention + output GEMM (mma.sync) ----------------
// smem map (bytes):
#define OQH 0u
#define OQL 9216u
#define OC0 18432u
#define OC1 18688u
#define ORED 18944u
#define OKV 20480u
#define KVB 73728u          // per buffer: Kh +0, Kl +18432, Vh +36864, Vl +55296
#define ATTN_SMEM (OKV + 2*KVB)
#define AP 72               // pitch in halves (144 B)

__global__ __launch_bounds__(256) void k_attn_mma(const float* __restrict__ bout,
                                                  float* __restrict__ out)
{
    extern __shared__ __align__(16) char smc[];
    const uint32_t sb = su32(smc);
    const int t = threadIdx.x, w = t>>5, lane = t&31;
    const int b = blockIdx.y, qbase = blockIdx.x*64;
    const int wm = w&1, wn = w>>1;            // wm: 2x32 q rows, wn: 4-way k/n split
    const int i8 = lane&7, q4 = lane>>3;
    const int mrow = i8 + ((q4&1)<<3), kcol = (q4>>1)<<3;
    const int s2 = (lane>>3)&1;
    const int g4 = lane>>2, tq = lane&3;

    auto issue = [&](int kc, int bf){
        uint32_t dbase = sb + OKV + (uint32_t)bf*KVB;
        size_t g0 = ((size_t)b*SQ + (size_t)kc*128)*DD;
#pragma unroll
        for (int i=0;i<4;++i){
            int id = t + i*256, row = id>>3, c = id&7;
            uint32_t doff = (uint32_t)(row*144 + c*16);
            size_t so = g0 + (size_t)row*DD + c*8;
            CPA(dbase + doff,          g_kh + so);
            CPA(dbase + 18432u + doff, g_kl + so);
            CPA(dbase + 36864u + doff, g_vh + so);
            CPA(dbase + 55296u + doff, g_vl + so);
        }
        CPC();
    };
    issue(0, 0);

    // Q tiles + layernorm constants
#pragma unroll
    for (int i=0;i<2;++i){
        int id = t + i*256, row = id>>3, c = id&7;
        size_t so = ((size_t)(b*SQ + qbase) + row)*DD + c*8;
        *(uint4*)(smc + OQH + row*144 + c*16) = *(const uint4*)(g_qh + so);
        *(uint4*)(smc + OQL + row*144 + c*16) = *(const uint4*)(g_ql + so);
    }
    if (t < 64){
        ((float*)(smc+OC0))[t] = g_c0[b*SQ + qbase + t];
        ((float*)(smc+OC1))[t] = g_c1[b*SQ + qbase + t];
    }
    __syncthreads();
    float c0v[2][2], c1v[2][2];
#pragma unroll
    for (int mt=0;mt<2;++mt)
#pragma unroll
        for (int hf=0;hf<2;++hf){
            int row = wm*32 + mt*16 + g4 + hf*8;
            c0v[mt][hf] = ((float*)(smc+OC0))[row];
            c1v[mt][hf] = ((float*)(smc+OC1))[row];
        }

    float oc[2][8][4];
#pragma unroll
    for (int a=0;a<2;++a)
#pragma unroll
        for (int n=0;n<8;++n)
#pragma unroll
            for (int c=0;c<4;++c) oc[a][n][c]=0.f;
    float lacc[4] = {0.f,0.f,0.f,0.f};

    for (int kc=0;kc<16;++kc){
        if (kc<15){ issue(kc+1, (kc+1)&1); CPW(1); } else { CPW(0); }
        __syncthreads();
        const uint32_t kb = sb + OKV + (uint32_t)((kc&1)*KVB);

        // S = Q K^T (hi/lo split)
        float sa[2][4][4];
#pragma unroll
        for (int a=0;a<2;++a)
#pragma unroll
            for (int n=0;n<4;++n)
#pragma unroll
                for (int c=0;c<4;++c) sa[a][n][c]=0.f;
#pragma unroll
        for (int ks=0;ks<4;++ks){
            uint32_t ah[2][4], al[2][4];
#pragma unroll
            for (int mt=0;mt<2;++mt){
                uint32_t ra = (uint32_t)(((wm*32+mt*16+mrow)*AP + ks*16 + kcol)*2);
                ldsm4(ah[mt][0],ah[mt][1],ah[mt][2],ah[mt][3], sb + OQH + ra);
                ldsm4(al[mt][0],al[mt][1],al[mt][2],al[mt][3], sb + OQL + ra);
            }
#pragma unroll
            for (int nt=0;nt<4;++nt){
                uint32_t rb = kb + (uint32_t)(((wn*32+nt*8+i8)*AP + ks*16 + s2*8)*2);
                uint32_t bh0,bh1,bl0,bl1;
                ldsm2(bh0,bh1, rb);
                ldsm2(bl0,bl1, rb + 18432u);
#pragma unroll
                for (int mt=0;mt<2;++mt){
                    mma16816(sa[mt][nt], ah[mt], bh0, bh1);
                    mma16816(sa[mt][nt], ah[mt], bl0, bl1);
                    mma16816(sa[mt][nt], al[mt], bh0, bh1);
                }
            }
        }
        // p = exp(s*c1 + c0), rowsum
#pragma unroll
        for (int mt=0;mt<2;++mt)
#pragma unroll
        for (int nt=0;nt<4;++nt){
            float* s4 = sa[mt][nt];
            s4[0] = __expf(fmaf(s4[0], c1v[mt][0], c0v[mt][0]));
            s4[1] = __expf(fmaf(s4[1], c1v[mt][0], c0v[mt][0]));
            s4[2] = __expf(fmaf(s4[2], c1v[mt][1], c0v[mt][1]));
            s4[3] = __expf(fmaf(s4[3], c1v[mt][1], c0v[mt][1]));
            lacc[mt*2+0] += s4[0]+s4[1];
            lacc[mt*2+1] += s4[2]+s4[3];
        }
        // O += P V  (S-frags reused as A-frags; V via ldmatrix.trans)
#pragma unroll
        for (int j=0;j<2;++j){
            uint32_t pah[2][4], pal[2][4];
#pragma unroll
            for (int mt=0;mt<2;++mt){
                split_pair(sa[mt][2*j][0],   sa[mt][2*j][1],   pah[mt][0], pal[mt][0]);
                split_pair(sa[mt][2*j][2],   sa[mt][2*j][3],   pah[mt][1], pal[mt][1]);
                split_pair(sa[mt][2*j+1][0], sa[mt][2*j+1][1], pah[mt][2], pal[mt][2]);
                split_pair(sa[mt][2*j+1][2], sa[mt][2*j+1][3], pah[mt][3], pal[mt][3]);
            }
#pragma unroll
            for (int nt=0;nt<8;++nt){
                uint32_t va = kb + 36864u +
                    (uint32_t)(((wn*32 + j*16 + i8 + s2*8)*AP + nt*8)*2);
                uint32_t bh0,bh1,bl0,bl1;
                ldsm2t(bh0,bh1, va);
                ldsm2t(bl0,bl1, va + 18432u);
#pragma unroll
                for (int mt=0;mt<2;++mt){
                    mma16816(oc[mt][nt], pah[mt], bh0, bh1);
                    mma16816(oc[mt][nt], pah[mt], bl0, bl1);
                    mma16816(oc[mt][nt], pal[mt], bh0, bh1);
                }
            }
        }
        __syncthreads();
    }

    // rowsum reduce across quad lanes, then across wn warps
#pragma unroll
    for (int i=0;i<4;++i){
        lacc[i] += __shfl_xor_sync(0xffffffffu, lacc[i], 1);
        lacc[i] += __shfl_xor_sync(0xffffffffu, lacc[i], 2);
    }
    if (tq == 0){
#pragma unroll
        for (int mt=0;mt<2;++mt)
#pragma unroll
            for (int hf=0;hf<2;++hf)
                ((float*)(smc+ORED))[wn*64 + wm*32 + mt*16 + g4 + hf*8] = lacc[mt*2+hf];
    }
    // partial O -> smem (reuses KV buffers)
    {
        float* ob = (float*)(smc + OKV + (size_t)wn*17408);
#pragma unroll
        for (int mt=0;mt<2;++mt)
#pragma unroll
        for (int nt=0;nt<8;++nt){
            int r0 = wm*32 + mt*16 + g4, cc = nt*8 + tq*2;
            *(float2*)&ob[r0*68 + cc]     = make_float2(oc[mt][nt][0], oc[mt][nt][1]);
            *(float2*)&ob[(r0+8)*68 + cc] = make_float2(oc[mt][nt][2], oc[mt][nt][3]);
        }
    }
    __syncthreads();
    if (t < 64){
        float s = 0.f;
#pragma unroll
        for (int wq=0;wq<4;++wq) s += ((float*)(smc+ORED))[wq*64 + t];
        ((float*)(smc+OC0))[t] = 1.f / s;
    }
    __syncthreads();
    // head = (sum_wn O) * linv -> f16 hi/lo over Q region
    for (int id = t; id < 2048; id += 256){
        int row = id >> 5, d2 = (id & 31) * 2;
        float o0 = 0.f, o1 = 0.f;
#pragma unroll
        for (int wq=0;wq<4;++wq){
            const float* ob = (const float*)(smc + OKV + (size_t)wq*17408);
            o0 += ob[row*68 + d2];
            o1 += ob[row*68 + d2 + 1];
        }
        float li = ((float*)(smc+OC0))[row];
        uint32_t hi, lo;
        split_pair(o0*li, o1*li, hi, lo);
        *(uint32_t*)(smc + OQH + row*144 + d2*2) = hi;
        *(uint32_t*)(smc + OQL + row*144 + d2*2) = lo;
    }

    // fused output GEMM: out = head @ Weff + bout
    float* orow = out + (size_t)(b*SQ + qbase)*HH;
    for (int jt=0;jt<8;++jt){
        __syncthreads();
#pragma unroll
        for (int i=0;i<4;++i){
            int id = t + i*256, row = id>>3, c = id&7;
            size_t so = (size_t)(jt*128 + row)*DD + c*8;
            *(uint4*)(smc + OKV + row*144 + c*16)          = *(const uint4*)(g_WeffTh + so);
            *(uint4*)(smc + OKV + 18432u + row*144 + c*16) = *(const uint4*)(g_WeffTl + so);
        }
        __syncthreads();
        float acc[2][4][4];
#pragma unroll
        for (int a=0;a<2;++a)
#pragma unroll
            for (int n=0;n<4;++n)
#pragma unroll
                for (int c=0;c<4;++c) acc[a][n][c]=0.f;
#pragma unroll
        for (int ks=0;ks<4;++ks){
            uint32_t ah[2][4], al[2][4];
#pragma unroll
            for (int mt=0;mt<2;++mt){
                uint32_t ra = (uint32_t)(((wm*32+mt*16+mrow)*AP + ks*16 + kcol)*2);
                ldsm4(ah[mt][0],ah[mt][1],ah[mt][2],ah[mt][3], sb + OQH + ra);
                ldsm4(al[mt][0],al[mt][1],al[mt][2],al[mt][3], sb + OQL + ra);
            }
#pragma unroll
            for (int nt=0;nt<4;++nt){
                uint32_t rb = sb + OKV + (uint32_t)(((wn*32+nt*8+i8)*AP + ks*16 + s2*8)*2);
                uint32_t bh0,bh1,bl0,bl1;
                ldsm2(bh0,bh1, rb);
                ldsm2(bl0,bl1, rb + 18432u);
#pragma unroll
                for (int mt=0;mt<2;++mt){
                    mma16816(acc[mt][nt], ah[mt], bh0, bh1);
                    mma16816(acc[mt][nt], ah[mt], bl0, bl1);
                    mma16816(acc[mt][nt], al[mt], bh0, bh1);
                }
            }
        }
#pragma unroll
        for (int mt=0;mt<2;++mt)
#pragma unroll
        for (int nt=0;nt<4;++nt){
            int col = jt*128 + wn*32 + nt*8 + tq*2;
            float2 bb = __ldg((const float2*)&bout[col]);
#pragma unroll
            for (int hf=0;hf<2;++hf){
                int row = wm*32 + mt*16 + g4 + hf*8;
                *(float2*)&orow[(size_t)row*HH + col] =
                    make_float2(acc[mt][nt][hf*2+0] + bb.x, acc[mt][nt][hf*2+1] + bb.y);
            }
        }
    }
}

// ---------------------------------------------------------------------------
extern "C" void kernel_launch(void* const* d_in, const int* in_sizes, int n_in,
                              void* d_out, int out_size)
{
    (void)in_sizes; (void)n_in; (void)out_size;
    const float* query = (const float*)d_in[0];
    const float* key   = (const float*)d_in[1];
    const float* value = (const float*)d_in[2];
    const float* Wq   = (const float*)d_in[4];
    const float* bq   = (const float*)d_in[5];
    const float* Wk   = (const float*)d_in[6];
    const float* bk   = (const float*)d_in[7];
    const float* Wv   = (const float*)d_in[8];
    const float* bv   = (const float*)d_in[9];
    const float* Wout = (const float*)d_in[10];
    const float* bo   = (const float*)d_in[11];
    float* out = (float*)d_out;

    cudaFuncSetAttribute(k_stats,    cudaFuncAttributeMaxDynamicSharedMemorySize, STATS_SMEM);
    cudaFuncSetAttribute(k_attn_mma, cudaFuncAttributeMaxDynamicSharedMemorySize, ATTN_SMEM);

    k_prep<<<1024, 256>>>(Wq, Wk, Wv, Wout);
    k_proj_mma<<<dim3(64,3), 256>>>(query, key, value, bq, bk, bv);
    k_gram<<<dim3(16,BB), 256>>>();
    k_gramred<<<66, 256>>>();
    k_stats<<<dim3(8,BB), 256, STATS_SMEM>>>();
    k_attn_mma<<<dim3(32,BB), 256, ATTN_SMEM>>>(bo, out);
}

// round 5
// speedup vs baseline: 4.3401x; 1.2682x over previous
#include <cuda_runtime.h>
#include <cuda_fp16.h>
#include <cstdint>
#include <math.h>

#define BB 4
#define SQ 2048
#define HH 1024
#define DD 64
#define MT (BB*SQ)   // 8192

// ---------------- scratch ----------------
__device__ __align__(16) __half g_qh[MT*DD], g_ql[MT*DD];
__device__ __align__(16) __half g_kh[MT*DD], g_kl[MT*DD];
__device__ __align__(16) __half g_vh[MT*DD];
__device__ __align__(16) __half g_WTh[3*DD*HH], g_WTl[3*DD*HH];   // [sel][n=64][k=1024]
__device__ __align__(16) __half g_WeffTh[HH*DD], g_WeffTl[HH*DD]; // [j=1024][d=64]
__device__ float g_Gpart[BB*16*DD*DD];
__device__ float g_Kspart[BB*16*DD];
__device__ float g_G[BB*DD*DD];
__device__ float g_Ksum[BB*DD];

// ---------------- helpers ----------------
__device__ __forceinline__ uint32_t su32(const void* p){
    uint32_t a;
    asm("{ .reg .u64 t; cvta.to.shared.u64 t, %1; cvt.u32.u64 %0, t; }" : "=r"(a) : "l"(p));
    return a;
}
__device__ __forceinline__ void ldsm4(uint32_t& r0,uint32_t& r1,uint32_t& r2,uint32_t& r3,uint32_t a){
    asm volatile("ldmatrix.sync.aligned.m8n8.x4.shared.b16 {%0,%1,%2,%3}, [%4];"
                 : "=r"(r0),"=r"(r1),"=r"(r2),"=r"(r3) : "r"(a));
}
__device__ __forceinline__ void ldsm2(uint32_t& r0,uint32_t& r1,uint32_t a){
    asm volatile("ldmatrix.sync.aligned.m8n8.x2.shared.b16 {%0,%1}, [%2];"
                 : "=r"(r0),"=r"(r1) : "r"(a));
}
__device__ __forceinline__ void ldsm2t(uint32_t& r0,uint32_t& r1,uint32_t a){
    asm volatile("ldmatrix.sync.aligned.m8n8.x2.trans.shared.b16 {%0,%1}, [%2];"
                 : "=r"(r0),"=r"(r1) : "r"(a));
}
__device__ __forceinline__ void mma16816(float* c, const uint32_t* a, uint32_t b0, uint32_t b1){
    asm volatile("mma.sync.aligned.m16n8k16.row.col.f32.f16.f16.f32 "
                 "{%0,%1,%2,%3}, {%4,%5,%6,%7}, {%8,%9}, {%0,%1,%2,%3};"
                 : "+f"(c[0]),"+f"(c[1]),"+f"(c[2]),"+f"(c[3])
                 : "r"(a[0]),"r"(a[1]),"r"(a[2]),"r"(a[3]), "r"(b0),"r"(b1));
}
#define CPA(dst,src) asm volatile("cp.async.cg.shared.global [%0], [%1], 16;" :: "r"(dst),"l"(src))
#define CPC() asm volatile("cp.async.commit_group;" ::: "memory")
#define CPW(n) asm volatile("cp.async.wait_group %0;" :: "n"(n) : "memory")

__device__ __forceinline__ uint32_t cvt2h(float x, float y){
    __half2 h = __floats2half2_rn(x,y);
    return *(uint32_t*)&h;
}
__device__ __forceinline__ void split_pair(float x, float y, uint32_t& hi, uint32_t& lo){
    __half2 h = __floats2half2_rn(x,y);
    float2 f = __half22float2(h);
    __half2 l = __floats2half2_rn(x - f.x, y - f.y);
    hi = *(uint32_t*)&h; lo = *(uint32_t*)&l;
}

// ---------------- prep: hi/lo W^T + folded Weff^T ----------------
__global__ void k_prep(const float* __restrict__ Wq, const float* __restrict__ Wk,
                       const float* __restrict__ Wv, const float* __restrict__ Wout){
    int idx = blockIdx.x*256 + threadIdx.x;   // 262144
    if (idx < 3*65536) {
        int w = idx >> 16, r = idx & 65535, n = r >> 10, k = r & 1023;
        const float* W = w==0 ? Wq : (w==1 ? Wk : Wv);
        float x = W[k*DD + n];
        __half h = __float2half(x);
        g_WTh[idx] = h;
        g_WTl[idx] = __float2half(x - __half2float(h));
    } else {
        int r = idx - 3*65536, j = r >> 6, d = r & 63;
        float s = 0.f;
#pragma unroll
        for (int h = 0; h < 16; ++h) s += Wout[(h*DD + d)*HH + j];
        __half hh = __float2half(s);
        g_WeffTh[j*DD + d] = hh;
        g_WeffTl[j*DD + d] = __float2half(s - __half2float(hh));
    }
}

// ---------------- projection via mma: X[8192,1024]@W[1024,64]+b ----------------
// X pure f16 (1 cvt per pair); W split hi/lo -> 2 MMAs per product.
#define PP 40   // pitch in halves (80 B)
__global__ __launch_bounds__(256) void k_proj_mma(
    const float* __restrict__ Xq, const float* __restrict__ Xk, const float* __restrict__ Xv,
    const float* __restrict__ bq, const float* __restrict__ bk, const float* __restrict__ bv)
{
    __shared__ __align__(16) __half Xh[128*PP];
    __shared__ __align__(16) __half Wh[64*PP], Wl[64*PP];

    const int t = threadIdx.x, w = t>>5, lane = t&31;
    const int sel = blockIdx.y, m0 = blockIdx.x*128;
    const int wm = w&3, wn = w>>2;
    const float* X    = sel==0?Xq:(sel==1?Xk:Xv);
    const float* bias = sel==0?bq:(sel==1?bk:bv);
    const __half* WTh = g_WTh + sel*65536;
    const __half* WTl = g_WTl + sel*65536;

    const int i8 = lane&7, q4 = lane>>3;
    const int mrow = i8 + ((q4&1)<<3), kcol = (q4>>1)<<3;
    const int s2 = (lane>>3)&1;
    const uint32_t xh_b = su32(Xh), wh_b = su32(Wh), wl_b = su32(Wl);

    float acc[2][4][4];
#pragma unroll
    for (int a=0;a<2;++a)
#pragma unroll
        for (int bq_=0;bq_<4;++bq_)
#pragma unroll
            for (int cq=0;cq<4;++cq) acc[a][bq_][cq]=0.f;

    float4 xr[4]; uint4 whr, wlr;
    auto LD = [&](int c){
        int k0 = c*32;
#pragma unroll
        for (int i=0;i<4;++i){ int id=t+i*256, row=id>>3, c4=id&7;
            xr[i] = *(const float4*)&X[(size_t)(m0+row)*HH + k0 + c4*4]; }
        { int row = t>>2, cc = t&3;
          whr = *(const uint4*)(WTh + (size_t)row*HH + k0 + cc*8);
          wlr = *(const uint4*)(WTl + (size_t)row*HH + k0 + cc*8); }
    };
    auto ST = [&](){
#pragma unroll
        for (int i=0;i<4;++i){ int id=t+i*256, row=id>>3, c4=id&7;
            *(uint2*)&Xh[row*PP + c4*4] =
                make_uint2(cvt2h(xr[i].x, xr[i].y), cvt2h(xr[i].z, xr[i].w)); }
        { int row = t>>2, cc = t&3;
          *(uint4*)&Wh[row*PP + cc*8] = whr;
          *(uint4*)&Wl[row*PP + cc*8] = wlr; }
    };

    LD(0); ST(); __syncthreads();
    for (int c=0;c<32;++c){
        if (c<31) LD(c+1);
#pragma unroll
        for (int ks=0;ks<2;++ks){
            uint32_t ah[2][4];
#pragma unroll
            for (int mt=0;mt<2;++mt){
                uint32_t ra = (uint32_t)(((wm*32+mt*16+mrow)*PP + ks*16 + kcol)*2);
                ldsm4(ah[mt][0],ah[mt][1],ah[mt][2],ah[mt][3], xh_b + ra);
            }
#pragma unroll
            for (int nt=0;nt<4;++nt){
                uint32_t rb = (uint32_t)(((wn*32+nt*8+i8)*PP + ks*16 + s2*8)*2);
                uint32_t bh0,bh1,bl0,bl1;
                ldsm2(bh0,bh1, wh_b + rb);
                ldsm2(bl0,bl1, wl_b + rb);
#pragma unroll
                for (int mt=0;mt<2;++mt){
                    mma16816(acc[mt][nt], ah[mt], bh0, bh1);
                    mma16816(acc[mt][nt], ah[mt], bl0, bl1);
                }
            }
        }
        __syncthreads();
        if (c<31){ ST(); __syncthreads(); }
    }

    // epilogue: q,k -> f16 hi/lo; v -> f16 only
    const int g4 = lane>>2, tq = lane&3;
#pragma unroll
    for (int mt=0;mt<2;++mt)
#pragma unroll
    for (int nt=0;nt<4;++nt){
        int n = wn*32 + nt*8 + tq*2;
        float2 bb = __ldg((const float2*)&bias[n]);
#pragma unroll
        for (int hf=0;hf<2;++hf){
            int row = m0 + wm*32 + mt*16 + g4 + hf*8;
            float v0 = acc[mt][nt][hf*2+0] + bb.x;
            float v1 = acc[mt][nt][hf*2+1] + bb.y;
            size_t o = (size_t)row*DD + n;
            if (sel < 2){
                uint32_t hi, lo;
                split_pair(v0, v1, hi, lo);
                __half* Oh = sel==0 ? g_qh : g_kh;
                __half* Ol = sel==0 ? g_ql : g_kl;
                *(uint32_t*)(Oh + o) = hi;
                *(uint32_t*)(Ol + o) = lo;
            } else {
                *(uint32_t*)(g_vh + o) = cvt2h(v0, v1);
            }
        }
    }
}

// ---------------- fp32 Gram (k reconstructed from hi+lo) ----------------
__global__ __launch_bounds__(256) void k_gram() {
    const int b = blockIdx.y, cb = blockIdx.x;
    __shared__ float Ks2[128*65];
    const int t = threadIdx.x;
    const size_t base = ((size_t)(b*SQ + cb*128))*DD;
    for (int id = t; id < 1024; id += 256) {
        int row = id >> 3, c = (id & 7) * 8;
        const __half2* h2 = (const __half2*)&g_kh[base + (size_t)row*DD + c];
        const __half2* l2 = (const __half2*)&g_kl[base + (size_t)row*DD + c];
#pragma unroll
        for (int j = 0; j < 4; ++j){
            float2 fh = __half22float2(h2[j]);
            float2 fl = __half22float2(l2[j]);
            Ks2[row*65 + c + 2*j]   = fh.x + fl.x;
            Ks2[row*65 + c + 2*j+1] = fh.y + fl.y;
        }
    }
    __syncthreads();
    int a = t >> 2, b0 = (t & 3) * 16;
    float acc[16];
#pragma unroll
    for (int i = 0; i < 16; ++i) acc[i] = 0.f;
    for (int j = 0; j < 128; ++j) {
        float ka = Ks2[j*65 + a];
#pragma unroll
        for (int bb = 0; bb < 16; ++bb) acc[bb] += ka * Ks2[j*65 + b0 + bb];
    }
    float* gp = g_Gpart + (size_t)(b*16 + cb)*4096;
#pragma unroll
    for (int bb = 0; bb < 16; ++bb) gp[a*64 + b0 + bb] = acc[bb];
    if (t < 64) {
        float s = 0.f;
        for (int j = 0; j < 128; ++j) s += Ks2[j*65 + t];
        g_Kspart[(b*16 + cb)*64 + t] = s;
    }
}
__global__ void k_gramred() {
    int idx = blockIdx.x * 256 + threadIdx.x;
    if (idx < BB*4096) {
        int b = idx >> 12, e = idx & 4095;
        float s = 0.f;
#pragma unroll
        for (int c = 0; c < 16; ++c) s += g_Gpart[(size_t)(b*16+c)*4096 + e];
        g_G[idx] = s;
    } else if (idx < BB*4096 + BB*64) {
        int r = idx - BB*4096, b = r >> 6, e = r & 63;
        float s = 0.f;
#pragma unroll
        for (int c = 0; c < 16; ++c) s += g_Kspart[(b*16+c)*64 + e];
        g_Ksum[r] = s;
    }
}

// ---------------- fused flash attention + stats + output GEMM ----------------
// smem map (bytes):
#define OQH 0u
#define OQL 9216u
#define OC0 18432u
#define OC1 18688u
#define ORED 18944u
#define OKV 20480u
#define KVB 55296u          // per buffer: Kh +0, Kl +18432, Vh +36864
#define ATTN_SMEM (OKV + 2*KVB)
#define AP 72               // pitch in halves (144 B)

__global__ __launch_bounds__(256) void k_attn_mma(const float* __restrict__ bout,
                                                  float* __restrict__ out)
{
    extern __shared__ __align__(16) char smc[];
    const uint32_t sb = su32(smc);
    const int t = threadIdx.x, w = t>>5, lane = t&31;
    const int b = blockIdx.y, qbase = blockIdx.x*64;
    const int wm = w&1, wn = w>>1;
    const int i8 = lane&7, q4 = lane>>3;
    const int mrow = i8 + ((q4&1)<<3), kcol = (q4>>1)<<3;
    const int s2 = (lane>>3)&1;
    const int g4 = lane>>2, tq = lane&3;

    auto issue = [&](int kc, int bf){
        uint32_t dbase = sb + OKV + (uint32_t)bf*KVB;
        size_t g0 = ((size_t)b*SQ + (size_t)kc*128)*DD;
#pragma unroll
        for (int i=0;i<4;++i){
            int id = t + i*256, row = id>>3, c = id&7;
            uint32_t doff = (uint32_t)(row*144 + c*16);
            size_t so = g0 + (size_t)row*DD + c*8;
            CPA(dbase + doff,          g_kh + so);
            CPA(dbase + 18432u + doff, g_kl + so);
            CPA(dbase + 36864u + doff, g_vh + so);
        }
        CPC();
    };
    issue(0, 0);

    // Q tiles
#pragma unroll
    for (int i=0;i<2;++i){
        int id = t + i*256, row = id>>3, c = id&7;
        size_t so = ((size_t)(b*SQ + qbase) + row)*DD + c*8;
        *(uint4*)(smc + OQH + row*144 + c*16) = *(const uint4*)(g_qh + so);
        *(uint4*)(smc + OQL + row*144 + c*16) = *(const uint4*)(g_ql + so);
    }
    // stats inputs into KV buffer 1: G[4096] floats, then qf32[64][68]
    float* Gs  = (float*)(smc + OKV + KVB);
    float* qf  = (float*)(smc + OKV + KVB + 16384u);
    float* Ksm = (float*)(smc + ORED);
    for (int id = t; id < 1024; id += 256)
        *(float4*)&Gs[id*4] = *(const float4*)&g_G[(size_t)b*4096 + id*4];
    if (t < 64) Ksm[t] = g_Ksum[b*64 + t];
    __syncthreads();
    // build fp32 q rows from hi+lo
    for (int id = t; id < 2048; id += 256){
        int row = id >> 5, d2 = (id & 31) * 2;
        __half2 h = *(__half2*)(smc + OQH + row*144 + d2*2);
        __half2 l = *(__half2*)(smc + OQL + row*144 + d2*2);
        float2 fh = __half22float2(h), fl = __half22float2(l);
        qf[row*68 + d2]   = fh.x + fl.x;
        qf[row*68 + d2+1] = fh.y + fl.y;
    }
    __syncthreads();
    // per-query layernorm constants (4 threads per query)
    {
        int q = t >> 2, seg = (t & 3) * 16;
        float su = 0.f, sq = 0.f;
        for (int a = seg; a < seg+16; ++a) {
            float qa = qf[q*68 + a];
            su += qa * Ksm[a];
            float ta = 0.f;
#pragma unroll 16
            for (int bb = 0; bb < 64; ++bb) ta += Gs[a*64 + bb] * qf[q*68 + bb];
            sq += qa * ta;
        }
        su += __shfl_xor_sync(0xffffffffu, su, 1);
        su += __shfl_xor_sync(0xffffffffu, su, 2);
        sq += __shfl_xor_sync(0xffffffffu, sq, 1);
        sq += __shfl_xor_sync(0xffffffffu, sq, 2);
        if ((t & 3) == 0){
            float mu  = su * (1.f/(32.f*(float)SQ));
            float var = (sq*(1.f/1024.f) - (float)SQ*mu*mu) * (1.f/((float)SQ - 1.f));
            float rinv = 1.f / (sqrtf(var) + 1e-8f);
            ((float*)(smc+OC1))[q] = rinv * (1.f/32.f);
            ((float*)(smc+OC0))[q] = -mu * rinv;
        }
    }
    __syncthreads();
    float c0v[2][2], c1v[2][2];
#pragma unroll
    for (int mt=0;mt<2;++mt)
#pragma unroll
        for (int hf=0;hf<2;++hf){
            int row = wm*32 + mt*16 + g4 + hf*8;
            c0v[mt][hf] = ((float*)(smc+OC0))[row];
            c1v[mt][hf] = ((float*)(smc+OC1))[row];
        }

    float oc[2][8][4];
#pragma unroll
    for (int a=0;a<2;++a)
#pragma unroll
        for (int n=0;n<8;++n)
#pragma unroll
            for (int c=0;c<4;++c) oc[a][n][c]=0.f;
    float lacc[4] = {0.f,0.f,0.f,0.f};

    for (int kc=0;kc<16;++kc){
        if (kc<15){ issue(kc+1, (kc+1)&1); CPW(1); } else { CPW(0); }
        __syncthreads();
        const uint32_t kb = sb + OKV + (uint32_t)((kc&1)*KVB);

        // S = Q K^T (q,k hi/lo: 3 MMAs)
        float sa[2][4][4];
#pragma unroll
        for (int a=0;a<2;++a)
#pragma unroll
            for (int n=0;n<4;++n)
#pragma unroll
                for (int c=0;c<4;++c) sa[a][n][c]=0.f;
#pragma unroll
        for (int ks=0;ks<4;++ks){
            uint32_t ah[2][4], al[2][4];
#pragma unroll
            for (int mt=0;mt<2;++mt){
                uint32_t ra = (uint32_t)(((wm*32+mt*16+mrow)*AP + ks*16 + kcol)*2);
                ldsm4(ah[mt][0],ah[mt][1],ah[mt][2],ah[mt][3], sb + OQH + ra);
                ldsm4(al[mt][0],al[mt][1],al[mt][2],al[mt][3], sb + OQL + ra);
            }
#pragma unroll
            for (int nt=0;nt<4;++nt){
                uint32_t rb = kb + (uint32_t)(((wn*32+nt*8+i8)*AP + ks*16 + s2*8)*2);
                uint32_t bh0,bh1,bl0,bl1;
                ldsm2(bh0,bh1, rb);
                ldsm2(bl0,bl1, rb + 18432u);
#pragma unroll
                for (int mt=0;mt<2;++mt){
                    mma16816(sa[mt][nt], ah[mt], bh0, bh1);
                    mma16816(sa[mt][nt], ah[mt], bl0, bl1);
                    mma16816(sa[mt][nt], al[mt], bh0, bh1);
                }
            }
        }
        // p = exp(s*c1 + c0), rowsum
#pragma unroll
        for (int mt=0;mt<2;++mt)
#pragma unroll
        for (int nt=0;nt<4;++nt){
            float* s4 = sa[mt][nt];
            s4[0] = __expf(fmaf(s4[0], c1v[mt][0], c0v[mt][0]));
            s4[1] = __expf(fmaf(s4[1], c1v[mt][0], c0v[mt][0]));
            s4[2] = __expf(fmaf(s4[2], c1v[mt][1], c0v[mt][1]));
            s4[3] = __expf(fmaf(s4[3], c1v[mt][1], c0v[mt][1]));
            lacc[mt*2+0] += s4[0]+s4[1];
            lacc[mt*2+1] += s4[2]+s4[3];
        }
        // O += P V  (P pure f16, V pure f16: 1 MMA)
#pragma unroll
        for (int j=0;j<2;++j){
            uint32_t pah[2][4];
#pragma unroll
            for (int mt=0;mt<2;++mt){
                pah[mt][0] = cvt2h(sa[mt][2*j][0],   sa[mt][2*j][1]);
                pah[mt][1] = cvt2h(sa[mt][2*j][2],   sa[mt][2*j][3]);
                pah[mt][2] = cvt2h(sa[mt][2*j+1][0], sa[mt][2*j+1][1]);
                pah[mt][3] = cvt2h(sa[mt][2*j+1][2], sa[mt][2*j+1][3]);
            }
#pragma unroll
            for (int nt=0;nt<8;++nt){
                uint32_t va = kb + 36864u +
                    (uint32_t)(((wn*32 + j*16 + i8 + s2*8)*AP + nt*8)*2);
                uint32_t bh0,bh1;
                ldsm2t(bh0,bh1, va);
#pragma unroll
                for (int mt=0;mt<2;++mt)
                    mma16816(oc[mt][nt], pah[mt], bh0, bh1);
            }
        }
        __syncthreads();
    }

    // rowsum reduce across quad, then across wn warps
#pragma unroll
    for (int i=0;i<4;++i){
        lacc[i] += __shfl_xor_sync(0xffffffffu, lacc[i], 1);
        lacc[i] += __shfl_xor_sync(0xffffffffu, lacc[i], 2);
    }
    if (tq == 0){
#pragma unroll
        for (int mt=0;mt<2;++mt)
#pragma unroll
            for (int hf=0;hf<2;++hf)
                ((float*)(smc+ORED))[wn*64 + wm*32 + mt*16 + g4 + hf*8] = lacc[mt*2+hf];
    }
    // partial O -> smem
    {
        float* ob = (float*)(smc + OKV + (size_t)wn*17408);
#pragma unroll
        for (int mt=0;mt<2;++mt)
#pragma unroll
        for (int nt=0;nt<8;++nt){
            int r0 = wm*32 + mt*16 + g4, cc = nt*8 + tq*2;
            *(float2*)&ob[r0*68 + cc]     = make_float2(oc[mt][nt][0], oc[mt][nt][1]);
            *(float2*)&ob[(r0+8)*68 + cc] = make_float2(oc[mt][nt][2], oc[mt][nt][3]);
        }
    }
    __syncthreads();
    if (t < 64){
        float s = 0.f;
#pragma unroll
        for (int wq=0;wq<4;++wq) s += ((float*)(smc+ORED))[wq*64 + t];
        ((float*)(smc+OC0))[t] = 1.f / s;
    }
    __syncthreads();
    // head = (sum O) * linv -> f16 hi/lo over Q region
    for (int id = t; id < 2048; id += 256){
        int row = id >> 5, d2 = (id & 31) * 2;
        float o0 = 0.f, o1 = 0.f;
#pragma unroll
        for (int wq=0;wq<4;++wq){
            const float* ob = (const float*)(smc + OKV + (size_t)wq*17408);
            o0 += ob[row*68 + d2];
            o1 += ob[row*68 + d2 + 1];
        }
        float li = ((float*)(smc+OC0))[row];
        uint32_t hi, lo;
        split_pair(o0*li, o1*li, hi, lo);
        *(uint32_t*)(smc + OQH + row*144 + d2*2) = hi;
        *(uint32_t*)(smc + OQL + row*144 + d2*2) = lo;
    }

    // fused output GEMM: out = head @ Weff + bout  (hi/lo 3 MMAs)
    float* orow = out + (size_t)(b*SQ + qbase)*HH;
    for (int jt=0;jt<8;++jt){
        __syncthreads();
#pragma unroll
        for (int i=0;i<4;++i){
            int id = t + i*256, row = id>>3, c = id&7;
            size_t so = (size_t)(jt*128 + row)*DD + c*8;
            *(uint4*)(smc + OKV + row*144 + c*16)          = *(const uint4*)(g_WeffTh + so);
            *(uint4*)(smc + OKV + 18432u + row*144 + c*16) = *(const uint4*)(g_WeffTl + so);
        }
        __syncthreads();
        float acc[2][4][4];
#pragma unroll
        for (int a=0;a<2;++a)
#pragma unroll
            for (int n=0;n<4;++n)
#pragma unroll
                for (int c=0;c<4;++c) acc[a][n][c]=0.f;
#pragma unroll
        for (int ks=0;ks<4;++ks){
            uint32_t ah[2][4], al[2][4];
#pragma unroll
            for (int mt=0;mt<2;++mt){
                uint32_t ra = (uint32_t)(((wm*32+mt*16+mrow)*AP + ks*16 + kcol)*2);
                ldsm4(ah[mt][0],ah[mt][1],ah[mt][2],ah[mt][3], sb + OQH + ra);
                ldsm4(al[mt][0],al[mt][1],al[mt][2],al[mt][3], sb + OQL + ra);
            }
#pragma unroll
            for (int nt=0;nt<4;++nt){
                uint32_t rb = sb + OKV + (uint32_t)(((wn*32+nt*8+i8)*AP + ks*16 + s2*8)*2);
                uint32_t bh0,bh1,bl0,bl1;
                ldsm2(bh0,bh1, rb);
                ldsm2(bl0,bl1, rb + 18432u);
#pragma unroll
                for (int mt=0;mt<2;++mt){
                    mma16816(acc[mt][nt], ah[mt], bh0, bh1);
                    mma16816(acc[mt][nt], ah[mt], bl0, bl1);
                    mma16816(acc[mt][nt], al[mt], bh0, bh1);
                }
            }
        }
#pragma unroll
        for (int mt=0;mt<2;++mt)
#pragma unroll
        for (int nt=0;nt<4;++nt){
            int col = jt*128 + wn*32 + nt*8 + tq*2;
            float2 bb = __ldg((const float2*)&bout[col]);
#pragma unroll
            for (int hf=0;hf<2;++hf){
                int row = wm*32 + mt*16 + g4 + hf*8;
                *(float2*)&orow[(size_t)row*HH + col] =
                    make_float2(acc[mt][nt][hf*2+0] + bb.x, acc[mt][nt][hf*2+1] + bb.y);
            }
        }
    }
}

// ---------------------------------------------------------------------------
extern "C" void kernel_launch(void* const* d_in, const int* in_sizes, int n_in,
                              void* d_out, int out_size)
{
    (void)in_sizes; (void)n_in; (void)out_size;
    const float* query = (const float*)d_in[0];
    const float* key   = (const float*)d_in[1];
    const float* value = (const float*)d_in[2];
    const float* Wq   = (const float*)d_in[4];
    const float* bq   = (const float*)d_in[5];
    const float* Wk   = (const float*)d_in[6];
    const float* bk   = (const float*)d_in[7];
    const float* Wv   = (const float*)d_in[8];
    const float* bv   = (const float*)d_in[9];
    const float* Wout = (const float*)d_in[10];
    const float* bo   = (const float*)d_in[11];
    float* out = (float*)d_out;

    cudaFuncSetAttribute(k_attn_mma, cudaFuncAttributeMaxDynamicSharedMemorySize, ATTN_SMEM);

    k_prep<<<1024, 256>>>(Wq, Wk, Wv, Wout);
    k_proj_mma<<<dim3(64,3), 256>>>(query, key, value, bq, bk, bv);
    k_gram<<<dim3(16,BB), 256>>>();
    k_gramred<<<66, 256>>>();
    k_attn_mma<<<dim3(32,BB), 256, ATTN_SMEM>>>(bo, out);
}

// round 7
// speedup vs baseline: 4.4514x; 1.0256x over previous
#include <cuda_runtime.h>
#include <cuda_fp16.h>
#include <cstdint>
#include <math.h>

#define BB 4
#define SQ 2048
#define HH 1024
#define DD 64
#define MT (BB*SQ)   // 8192

// ---------------- scratch ----------------
__device__ __align__(16) __half g_qh[MT*DD];
__device__ __align__(16) __half g_kh[MT*DD], g_kl[MT*DD];
__device__ __align__(16) __half g_vh[MT*DD];
__device__ __align__(16) __half g_WTh[3*DD*HH], g_WTl[3*DD*HH];   // [sel][n=64][k=1024]
__device__ __align__(16) __half g_WeffTh[HH*DD], g_WeffTl[HH*DD]; // [j=1024][d=64]
__device__ float g_Gpart[BB*16*DD*DD];
__device__ float g_Kspart[BB*16*DD];
__device__ float g_G[BB*DD*DD];
__device__ float g_Ksum[BB*DD];

// ---------------- helpers ----------------
__device__ __forceinline__ uint32_t su32(const void* p){
    uint32_t a;
    asm("{ .reg .u64 t; cvta.to.shared.u64 t, %1; cvt.u32.u64 %0, t; }" : "=r"(a) : "l"(p));
    return a;
}
__device__ __forceinline__ void ldsm4(uint32_t& r0,uint32_t& r1,uint32_t& r2,uint32_t& r3,uint32_t a){
    asm volatile("ldmatrix.sync.aligned.m8n8.x4.shared.b16 {%0,%1,%2,%3}, [%4];"
                 : "=r"(r0),"=r"(r1),"=r"(r2),"=r"(r3) : "r"(a));
}
__device__ __forceinline__ void ldsm2(uint32_t& r0,uint32_t& r1,uint32_t a){
    asm volatile("ldmatrix.sync.aligned.m8n8.x2.shared.b16 {%0,%1}, [%2];"
                 : "=r"(r0),"=r"(r1) : "r"(a));
}
__device__ __forceinline__ void ldsm2t(uint32_t& r0,uint32_t& r1,uint32_t a){
    asm volatile("ldmatrix.sync.aligned.m8n8.x2.trans.shared.b16 {%0,%1}, [%2];"
                 : "=r"(r0),"=r"(r1) : "r"(a));
}
__device__ __forceinline__ void mma16816(float* c, const uint32_t* a, uint32_t b0, uint32_t b1){
    asm volatile("mma.sync.aligned.m16n8k16.row.col.f32.f16.f16.f32 "
                 "{%0,%1,%2,%3}, {%4,%5,%6,%7}, {%8,%9}, {%0,%1,%2,%3};"
                 : "+f"(c[0]),"+f"(c[1]),"+f"(c[2]),"+f"(c[3])
                 : "r"(a[0]),"r"(a[1]),"r"(a[2]),"r"(a[3]), "r"(b0),"r"(b1));
}
#define CPA(dst,src) asm volatile("cp.async.cg.shared.global [%0], [%1], 16;" :: "r"(dst),"l"(src))
#define CPC() asm volatile("cp.async.commit_group;" ::: "memory")
#define CPW(n) asm volatile("cp.async.wait_group %0;" :: "n"(n) : "memory")

__device__ __forceinline__ uint32_t cvt2h(float x, float y){
    __half2 h = __floats2half2_rn(x,y);
    return *(uint32_t*)&h;
}
__device__ __forceinline__ void split_pair(float x, float y, uint32_t& hi, uint32_t& lo){
    __half2 h = __floats2half2_rn(x,y);
    float2 f = __half22float2(h);
    __half2 l = __floats2half2_rn(x - f.x, y - f.y);
    hi = *(uint32_t*)&h; lo = *(uint32_t*)&l;
}

// ---------------- prep: hi/lo W^T + folded Weff^T ----------------
__global__ void k_prep(const float* __restrict__ Wq, const float* __restrict__ Wk,
                       const float* __restrict__ Wv, const float* __restrict__ Wout){
    int idx = blockIdx.x*256 + threadIdx.x;   // 262144
    if (idx < 3*65536) {
        int w = idx >> 16, r = idx & 65535, n = r >> 10, k = r & 1023;
        const float* W = w==0 ? Wq : (w==1 ? Wk : Wv);
        float x = W[k*DD + n];
        __half h = __float2half(x);
        g_WTh[idx] = h;
        g_WTl[idx] = __float2half(x - __half2float(h));
    } else {
        int r = idx - 3*65536, j = r >> 6, d = r & 63;
        float s = 0.f;
#pragma unroll
        for (int h = 0; h < 16; ++h) s += Wout[(h*DD + d)*HH + j];
        __half hh = __float2half(s);
        g_WeffTh[j*DD + d] = hh;
        g_WeffTl[j*DD + d] = __float2half(s - __half2float(hh));
    }
}

// ---------------- projection via mma + fused Gram (sel==1) ----------------
#define PP 40   // pitch in halves (80 B)
__global__ __launch_bounds__(256) void k_proj_mma(
    const float* __restrict__ Xq, const float* __restrict__ Xk, const float* __restrict__ Xv,
    const float* __restrict__ bq, const float* __restrict__ bk, const float* __restrict__ bv)
{
    // union: main loop uses Xh|Wh|Wl; gram stage uses 128x65 floats
    __shared__ __align__(16) char pbuf[33536];
    __half* Xh = (__half*)pbuf;
    __half* Wh = (__half*)(pbuf + 10240);
    __half* Wl = (__half*)(pbuf + 15360);
    float*  Ks2 = (float*)pbuf;

    const int t = threadIdx.x, w = t>>5, lane = t&31;
    const int sel = blockIdx.y, m0 = blockIdx.x*128;
    const int wm = w&3, wn = w>>2;
    const float* X    = sel==0?Xq:(sel==1?Xk:Xv);
    const float* bias = sel==0?bq:(sel==1?bk:bv);
    const __half* WTh = g_WTh + sel*65536;
    const __half* WTl = g_WTl + sel*65536;

    const int i8 = lane&7, q4 = lane>>3;
    const int mrow = i8 + ((q4&1)<<3), kcol = (q4>>1)<<3;
    const int s2 = (lane>>3)&1;
    const uint32_t xh_b = su32(Xh), wh_b = su32(Wh), wl_b = su32(Wl);

    float acc[2][4][4];
#pragma unroll
    for (int a=0;a<2;++a)
#pragma unroll
        for (int bq_=0;bq_<4;++bq_)
#pragma unroll
            for (int cq=0;cq<4;++cq) acc[a][bq_][cq]=0.f;

    float4 xr[4]; uint4 whr, wlr;
    auto LD = [&](int c){
        int k0 = c*32;
#pragma unroll
        for (int i=0;i<4;++i){ int id=t+i*256, row=id>>3, c4=id&7;
            xr[i] = *(const float4*)&X[(size_t)(m0+row)*HH + k0 + c4*4]; }
        { int row = t>>2, cc = t&3;
          whr = *(const uint4*)(WTh + (size_t)row*HH + k0 + cc*8);
          wlr = *(const uint4*)(WTl + (size_t)row*HH + k0 + cc*8); }
    };
    auto ST = [&](){
#pragma unroll
        for (int i=0;i<4;++i){ int id=t+i*256, row=id>>3, c4=id&7;
            *(uint2*)&Xh[row*PP + c4*4] =
                make_uint2(cvt2h(xr[i].x, xr[i].y), cvt2h(xr[i].z, xr[i].w)); }
        { int row = t>>2, cc = t&3;
          *(uint4*)&Wh[row*PP + cc*8] = whr;
          *(uint4*)&Wl[row*PP + cc*8] = wlr; }
    };

    LD(0); ST(); __syncthreads();
    for (int c=0;c<32;++c){
        if (c<31) LD(c+1);
#pragma unroll
        for (int ks=0;ks<2;++ks){
            uint32_t ah[2][4];
#pragma unroll
            for (int mt=0;mt<2;++mt){
                uint32_t ra = (uint32_t)(((wm*32+mt*16+mrow)*PP + ks*16 + kcol)*2);
                ldsm4(ah[mt][0],ah[mt][1],ah[mt][2],ah[mt][3], xh_b + ra);
            }
#pragma unroll
            for (int nt=0;nt<4;++nt){
                uint32_t rb = (uint32_t)(((wn*32+nt*8+i8)*PP + ks*16 + s2*8)*2);
                uint32_t bh0,bh1,bl0,bl1;
                ldsm2(bh0,bh1, wh_b + rb);
                ldsm2(bl0,bl1, wl_b + rb);
#pragma unroll
                for (int mt=0;mt<2;++mt){
                    mma16816(acc[mt][nt], ah[mt], bh0, bh1);
                    mma16816(acc[mt][nt], ah[mt], bl0, bl1);
                }
            }
        }
        __syncthreads();
        if (c<31){ ST(); __syncthreads(); }
    }

    // epilogue: q -> f16; k -> f16 hi/lo (+ fp32 gram stage); v -> f16
    const int g4 = lane>>2, tq = lane&3;
#pragma unroll
    for (int mt=0;mt<2;++mt)
#pragma unroll
    for (int nt=0;nt<4;++nt){
        int n = wn*32 + nt*8 + tq*2;
        float2 bb = __ldg((const float2*)&bias[n]);
#pragma unroll
        for (int hf=0;hf<2;++hf){
            int rowl = wm*32 + mt*16 + g4 + hf*8;
            float v0 = acc[mt][nt][hf*2+0] + bb.x;
            float v1 = acc[mt][nt][hf*2+1] + bb.y;
            size_t o = (size_t)(m0 + rowl)*DD + n;
            if (sel == 0){
                *(uint32_t*)(g_qh + o) = cvt2h(v0, v1);
            } else if (sel == 1){
                uint32_t hi, lo;
                split_pair(v0, v1, hi, lo);
                *(uint32_t*)(g_kh + o) = hi;
                *(uint32_t*)(g_kl + o) = lo;
                Ks2[rowl*65 + n]   = v0;
                Ks2[rowl*65 + n+1] = v1;
            } else {
                *(uint32_t*)(g_vh + o) = cvt2h(v0, v1);
            }
        }
    }

    if (sel == 1){
        __syncthreads();
        int a = t >> 2, b0 = (t & 3) * 16;
        float gacc[16];
#pragma unroll
        for (int i = 0; i < 16; ++i) gacc[i] = 0.f;
        for (int j = 0; j < 128; ++j) {
            float ka = Ks2[j*65 + a];
#pragma unroll
            for (int bb = 0; bb < 16; ++bb) gacc[bb] += ka * Ks2[j*65 + b0 + bb];
        }
        int bB = m0 >> 11, cb = (m0 >> 7) & 15;
        float* gp = g_Gpart + (size_t)(bB*16 + cb)*4096;
#pragma unroll
        for (int bb = 0; bb < 16; ++bb) gp[a*64 + b0 + bb] = gacc[bb];
        if (t < 64) {
            float s = 0.f;
            for (int j = 0; j < 128; ++j) s += Ks2[j*65 + t];
            g_Kspart[(bB*16 + cb)*64 + t] = s;
        }
    }
}

// ---------------- Gram reduce ----------------
__global__ void k_gramred() {
    int idx = blockIdx.x * 256 + threadIdx.x;
    if (idx < BB*4096) {
        int b = idx >> 12, e = idx & 4095;
        float s = 0.f;
#pragma unroll
        for (int c = 0; c < 16; ++c) s += g_Gpart[(size_t)(b*16+c)*4096 + e];
        g_G[idx] = s;
    } else if (idx < BB*4096 + BB*64) {
        int r = idx - BB*4096, b = r >> 6, e = r & 63;
        float s = 0.f;
#pragma unroll
        for (int c = 0; c < 16; ++c) s += g_Kspart[(b*16+c)*64 + e];
        g_Ksum[r] = s;
    }
}

// ---------------- fused flash attention + stats + output GEMM ----------------
// smem map (bytes):
#define OQH 0u
#define OQL 9216u           // head-lo only (never loaded for Q)
#define OC0 18432u
#define OC1 18688u
#define ORED 18944u
#define OKV 20480u
#define KVB 55296u          // per buffer: Kh +0, Kl +18432, Vh +36864
#define ATTN_SMEM (OKV + 2*KVB)
#define AP 72               // pitch in halves (144 B)

__global__ __launch_bounds__(256) void k_attn_mma(const float* __restrict__ bout,
                                                  float* __restrict__ out)
{
    extern __shared__ __align__(16) char smc[];
    const uint32_t sb = su32(smc);
    const int t = threadIdx.x, w = t>>5, lane = t&31;
    const int b = blockIdx.y, qbase = blockIdx.x*64;
    const int wm = w&1, wn = w>>1;
    const int i8 = lane&7, q4 = lane>>3;
    const int mrow = i8 + ((q4&1)<<3), kcol = (q4>>1)<<3;
    const int s2 = (lane>>3)&1;
    const int g4 = lane>>2, tq = lane&3;

    auto issue = [&](int kc, int bf){
        uint32_t dbase = sb + OKV + (uint32_t)bf*KVB;
        size_t g0 = ((size_t)b*SQ + (size_t)kc*128)*DD;
#pragma unroll
        for (int i=0;i<4;++i){
            int id = t + i*256, row = id>>3, c = id&7;
            uint32_t doff = (uint32_t)(row*144 + c*16);
            size_t so = g0 + (size_t)row*DD + c*8;
            CPA(dbase + doff,          g_kh + so);
            CPA(dbase + 18432u + doff, g_kl + so);
            CPA(dbase + 36864u + doff, g_vh + so);
        }
        CPC();
    };
    issue(0, 0);

    // Q tile (f16 only)
#pragma unroll
    for (int i=0;i<2;++i){
        int id = t + i*256, row = id>>3, c = id&7;
        size_t so = ((size_t)(b*SQ + qbase) + row)*DD + c*8;
        *(uint4*)(smc + OQH + row*144 + c*16) = *(const uint4*)(g_qh + so);
    }
    // stats inputs in KV buffer 1: G[4096] floats, then qf32[64][68]
    float* Gs  = (float*)(smc + OKV + KVB);
    float* qf  = (float*)(smc + OKV + KVB + 16384u);
    float* Ksm = (float*)(smc + ORED);
    for (int id = t; id < 1024; id += 256)
        *(float4*)&Gs[id*4] = *(const float4*)&g_G[(size_t)b*4096 + id*4];
    if (t < 64) Ksm[t] = g_Ksum[b*64 + t];
    __syncthreads();
    // fp32 q rows from qh
    for (int id = t; id < 2048; id += 256){
        int row = id >> 5, d2 = (id & 31) * 2;
        __half2 h = *(__half2*)(smc + OQH + row*144 + d2*2);
        float2 fh = __half22float2(h);
        qf[row*68 + d2]   = fh.x;
        qf[row*68 + d2+1] = fh.y;
    }
    __syncthreads();
    // per-query layernorm constants (4 threads per query)
    {
        int q = t >> 2, seg = (t & 3) * 16;
        float su = 0.f, sq = 0.f;
        for (int a = seg; a < seg+16; ++a) {
            float qa = qf[q*68 + a];
            su += qa * Ksm[a];
            float ta = 0.f;
#pragma unroll 16
            for (int bb = 0; bb < 64; ++bb) ta += Gs[a*64 + bb] * qf[q*68 + bb];
            sq += qa * ta;
        }
        su += __shfl_xor_sync(0xffffffffu, su, 1);
        su += __shfl_xor_sync(0xffffffffu, su, 2);
        sq += __shfl_xor_sync(0xffffffffu, sq, 1);
        sq += __shfl_xor_sync(0xffffffffu, sq, 2);
        if ((t & 3) == 0){
            float mu  = su * (1.f/(32.f*(float)SQ));
            float var = (sq*(1.f/1024.f) - (float)SQ*mu*mu) * (1.f/((float)SQ - 1.f));
            float rinv = 1.f / (sqrtf(var) + 1e-8f);
            ((float*)(smc+OC1))[q] = rinv * (1.f/32.f);
            ((float*)(smc+OC0))[q] = -mu * rinv;
        }
    }
    __syncthreads();
    float c0v[2][2], c1v[2][2];
#pragma unroll
    for (int mt=0;mt<2;++mt)
#pragma unroll
        for (int hf=0;hf<2;++hf){
            int row = wm*32 + mt*16 + g4 + hf*8;
            c0v[mt][hf] = ((float*)(smc+OC0))[row];
            c1v[mt][hf] = ((float*)(smc+OC1))[row];
        }

    float oc[2][8][4];
#pragma unroll
    for (int a=0;a<2;++a)
#pragma unroll
        for (int n=0;n<8;++n)
#pragma unroll
            for (int c=0;c<4;++c) oc[a][n][c]=0.f;
    float lacc[4] = {0.f,0.f,0.f,0.f};

    for (int kc=0;kc<16;++kc){
        if (kc<15){ issue(kc+1, (kc+1)&1); CPW(1); } else { CPW(0); }
        __syncthreads();
        const uint32_t kb = sb + OKV + (uint32_t)((kc&1)*KVB);

        // S = Q K^T  (q f16; k hi/lo: 2 MMAs)
        float sa[2][4][4];
#pragma unroll
        for (int a=0;a<2;++a)
#pragma unroll
            for (int n=0;n<4;++n)
#pragma unroll
                for (int c=0;c<4;++c) sa[a][n][c]=0.f;
#pragma unroll
        for (int ks=0;ks<4;++ks){
            uint32_t ah[2][4];
#pragma unroll
            for (int mt=0;mt<2;++mt){
                uint32_t ra = (uint32_t)(((wm*32+mt*16+mrow)*AP + ks*16 + kcol)*2);
                ldsm4(ah[mt][0],ah[mt][1],ah[mt][2],ah[mt][3], sb + OQH + ra);
            }
#pragma unroll
            for (int nt=0;nt<4;++nt){
                uint32_t rb = kb + (uint32_t)(((wn*32+nt*8+i8)*AP + ks*16 + s2*8)*2);
                uint32_t bh0,bh1,bl0,bl1;
                ldsm2(bh0,bh1, rb);
                ldsm2(bl0,bl1, rb + 18432u);
#pragma unroll
                for (int mt=0;mt<2;++mt){
                    mma16816(sa[mt][nt], ah[mt], bh0, bh1);
                    mma16816(sa[mt][nt], ah[mt], bl0, bl1);
                }
            }
        }
        // p = exp(s*c1 + c0), rowsum
#pragma unroll
        for (int mt=0;mt<2;++mt)
#pragma unroll
        for (int nt=0;nt<4;++nt){
            float* s4 = sa[mt][nt];
            s4[0] = __expf(fmaf(s4[0], c1v[mt][0], c0v[mt][0]));
            s4[1] = __expf(fmaf(s4[1], c1v[mt][0], c0v[mt][0]));
            s4[2] = __expf(fmaf(s4[2], c1v[mt][1], c0v[mt][1]));
            s4[3] = __expf(fmaf(s4[3], c1v[mt][1], c0v[mt][1]));
            lacc[mt*2+0] += s4[0]+s4[1];
            lacc[mt*2+1] += s4[2]+s4[3];
        }
        // O += P V  (P,V pure f16: 1 MMA)
#pragma unroll
        for (int j=0;j<2;++j){
            uint32_t pah[2][4];
#pragma unroll
            for (int mt=0;mt<2;++mt){
                pah[mt][0] = cvt2h(sa[mt][2*j][0],   sa[mt][2*j][1]);
                pah[mt][1] = cvt2h(sa[mt][2*j][2],   sa[mt][2*j][3]);
                pah[mt][2] = cvt2h(sa[mt][2*j+1][0], sa[mt][2*j+1][1]);
                pah[mt][3] = cvt2h(sa[mt][2*j+1][2], sa[mt][2*j+1][3]);
            }
#pragma unroll
            for (int nt=0;nt<8;++nt){
                uint32_t va = kb + 36864u +
                    (uint32_t)(((wn*32 + j*16 + i8 + s2*8)*AP + nt*8)*2);
                uint32_t bh0,bh1;
                ldsm2t(bh0,bh1, va);
#pragma unroll
                for (int mt=0;mt<2;++mt)
                    mma16816(oc[mt][nt], pah[mt], bh0, bh1);
            }
        }
        __syncthreads();
    }

    // rowsum reduce across quad, then across wn warps
#pragma unroll
    for (int i=0;i<4;++i){
        lacc[i] += __shfl_xor_sync(0xffffffffu, lacc[i], 1);
        lacc[i] += __shfl_xor_sync(0xffffffffu, lacc[i], 2);
    }
    if (tq == 0){
#pragma unroll
        for (int mt=0;mt<2;++mt)
#pragma unroll
            for (int hf=0;hf<2;++hf)
                ((float*)(smc+ORED))[wn*64 + wm*32 + mt*16 + g4 + hf*8] = lacc[mt*2+hf];
    }
    // partial O -> smem
    {
        float* ob = (float*)(smc + OKV + (size_t)wn*17408);
#pragma unroll
        for (int mt=0;mt<2;++mt)
#pragma unroll
        for (int nt=0;nt<8;++nt){
            int r0 = wm*32 + mt*16 + g4, cc = nt*8 + tq*2;
            *(float2*)&ob[r0*68 + cc]     = make_float2(oc[mt][nt][0], oc[mt][nt][1]);
            *(float2*)&ob[(r0+8)*68 + cc] = make_float2(oc[mt][nt][2], oc[mt][nt][3]);
        }
    }
    __syncthreads();
    if (t < 64){
        float s = 0.f;
#pragma unroll
        for (int wq=0;wq<4;++wq) s += ((float*)(smc+ORED))[wq*64 + t];
        ((float*)(smc+OC0))[t] = 1.f / s;
    }
    __syncthreads();
    // head = (sum O) * linv -> f16 hi/lo (hi in OQH, lo in OQL)
    for (int id = t; id < 2048; id += 256){
        int row = id >> 5, d2 = (id & 31) * 2;
        float o0 = 0.f, o1 = 0.f;
#pragma unroll
        for (int wq=0;wq<4;++wq){
            const float* ob = (const float*)(smc + OKV + (size_t)wq*17408);
            o0 += ob[row*68 + d2];
            o1 += ob[row*68 + d2 + 1];
        }
        float li = ((float*)(smc+OC0))[row];
        uint32_t hi, lo;
        split_pair(o0*li, o1*li, hi, lo);
        *(uint32_t*)(smc + OQH + row*144 + d2*2) = hi;
        *(uint32_t*)(smc + OQL + row*144 + d2*2) = lo;
    }

    // fused output GEMM: out = head @ Weff + bout  (head hi/lo 3 MMAs)
    float* stage = (float*)(smc + OKV + 40960u);   // 64 x 132 floats (pitch mult of 4)
    float* orow = out + (size_t)(b*SQ + qbase)*HH;
    for (int jt=0;jt<8;++jt){
        __syncthreads();
#pragma unroll
        for (int i=0;i<4;++i){
            int id = t + i*256, row = id>>3, c = id&7;
            size_t so = (size_t)(jt*128 + row)*DD + c*8;
            *(uint4*)(smc + OKV + row*144 + c*16)          = *(const uint4*)(g_WeffTh + so);
            *(uint4*)(smc + OKV + 18432u + row*144 + c*16) = *(const uint4*)(g_WeffTl + so);
        }
        __syncthreads();
        float acc[2][4][4];
#pragma unroll
        for (int a=0;a<2;++a)
#pragma unroll
            for (int n=0;n<4;++n)
#pragma unroll
                for (int c=0;c<4;++c) acc[a][n][c]=0.f;
#pragma unroll
        for (int ks=0;ks<4;++ks){
            uint32_t ah[2][4], al[2][4];
#pragma unroll
            for (int mt=0;mt<2;++mt){
                uint32_t ra = (uint32_t)(((wm*32+mt*16+mrow)*AP + ks*16 + kcol)*2);
                ldsm4(ah[mt][0],ah[mt][1],ah[mt][2],ah[mt][3], sb + OQH + ra);
                ldsm4(al[mt][0],al[mt][1],al[mt][2],al[mt][3], sb + OQL + ra);
            }
#pragma unroll
            for (int nt=0;nt<4;++nt){
                uint32_t rb = sb + OKV + (uint32_t)(((wn*32+nt*8+i8)*AP + ks*16 + s2*8)*2);
                uint32_t bh0,bh1,bl0,bl1;
                ldsm2(bh0,bh1, rb);
                ldsm2(bl0,bl1, rb + 18432u);
#pragma unroll
                for (int mt=0;mt<2;++mt){
                    mma16816(acc[mt][nt], ah[mt], bh0, bh1);
                    mma16816(acc[mt][nt], ah[mt], bl0, bl1);
                    mma16816(acc[mt][nt], al[mt], bh0, bh1);
                }
            }
        }
        // stage full 64x128 block with bias (pitch 132: float2/float4 aligned)
#pragma unroll
        for (int mt=0;mt<2;++mt)
#pragma unroll
        for (int nt=0;nt<4;++nt){
            int colL = wn*32 + nt*8 + tq*2;
            float2 bb = __ldg((const float2*)&bout[jt*128 + colL]);
#pragma unroll
            for (int hf=0;hf<2;++hf){
                int row = wm*32 + mt*16 + g4 + hf*8;
                *(float2*)&stage[row*132 + colL] =
                    make_float2(acc[mt][nt][hf*2+0] + bb.x, acc[mt][nt][hf*2+1] + bb.y);
            }
        }
        __syncthreads();
        // coalesced global write
#pragma unroll
        for (int i=0;i<8;++i){
            int id = t + i*256, row = id>>5, c4 = (id&31)*4;
            *(float4*)&orow[(size_t)row*HH + jt*128 + c4] = *(float4*)&stage[row*132 + c4];
        }
    }
}

// ---------------------------------------------------------------------------
extern "C" void kernel_launch(void* const* d_in, const int* in_sizes, int n_in,
                              void* d_out, int out_size)
{
    (void)in_sizes; (void)n_in; (void)out_size;
    const float* query = (const float*)d_in[0];
    const float* key   = (const float*)d_in[1];
    const float* value = (const float*)d_in[2];
    const float* Wq   = (const float*)d_in[4];
    const float* bq   = (const float*)d_in[5];
    const float* Wk   = (const float*)d_in[6];
    const float* bk   = (const float*)d_in[7];
    const float* Wv   = (const float*)d_in[8];
    const float* bv   = (const float*)d_in[9];
    const float* Wout = (const float*)d_in[10];
    const float* bo   = (const float*)d_in[11];
    float* out = (float*)d_out;

    cudaFuncSetAttribute(k_attn_mma, cudaFuncAttributeMaxDynamicSharedMemorySize, ATTN_SMEM);

    k_prep<<<1024, 256>>>(Wq, Wk, Wv, Wout);
    k_proj_mma<<<dim3(64,3), 256>>>(query, key, value, bq, bk, bv);
    k_gramred<<<66, 256>>>();
    k_attn_mma<<<dim3(32,BB), 256, ATTN_SMEM>>>(bo, out);
}

// round 10
// speedup vs baseline: 4.5392x; 1.0197x over previous
#include <cuda_runtime.h>
#include <cuda_fp16.h>
#include <cstdint>
#include <math.h>

#define BB 4
#define SQ 2048
#define HH 1024
#define DD 64
#define MT (BB*SQ)   // 8192

// ---------------- scratch ----------------
__device__ __align__(16) __half g_qh[MT*DD];
__device__ __align__(16) __half g_kh[MT*DD];
__device__ __align__(16) __half g_vh[MT*DD];
__device__ __align__(16) __half g_WTh[3*DD*HH], g_WTl[3*DD*HH];   // [sel][n=64][k=1024]
__device__ __align__(16) __half g_WeffTh[HH*DD], g_WeffTl[HH*DD]; // [j=1024][d=64]
__device__ float g_Gpart[BB*16*DD*DD];
__device__ float g_Kspart[BB*16*DD];
__device__ float g_G[BB*DD*DD];
__device__ float g_Ksum[BB*DD];

// ---------------- helpers ----------------
__device__ __forceinline__ uint32_t su32(const void* p){
    uint32_t a;
    asm("{ .reg .u64 t; cvta.to.shared.u64 t, %1; cvt.u32.u64 %0, t; }" : "=r"(a) : "l"(p));
    return a;
}
__device__ __forceinline__ void ldsm4(uint32_t& r0,uint32_t& r1,uint32_t& r2,uint32_t& r3,uint32_t a){
    asm volatile("ldmatrix.sync.aligned.m8n8.x4.shared.b16 {%0,%1,%2,%3}, [%4];"
                 : "=r"(r0),"=r"(r1),"=r"(r2),"=r"(r3) : "r"(a));
}
__device__ __forceinline__ void ldsm2(uint32_t& r0,uint32_t& r1,uint32_t a){
    asm volatile("ldmatrix.sync.aligned.m8n8.x2.shared.b16 {%0,%1}, [%2];"
                 : "=r"(r0),"=r"(r1) : "r"(a));
}
__device__ __forceinline__ void ldsm2t(uint32_t& r0,uint32_t& r1,uint32_t a){
    asm volatile("ldmatrix.sync.aligned.m8n8.x2.trans.shared.b16 {%0,%1}, [%2];"
                 : "=r"(r0),"=r"(r1) : "r"(a));
}
__device__ __forceinline__ void mma16816(float* c, const uint32_t* a, uint32_t b0, uint32_t b1){
    asm volatile("mma.sync.aligned.m16n8k16.row.col.f32.f16.f16.f32 "
                 "{%0,%1,%2,%3}, {%4,%5,%6,%7}, {%8,%9}, {%0,%1,%2,%3};"
                 : "+f"(c[0]),"+f"(c[1]),"+f"(c[2]),"+f"(c[3])
                 : "r"(a[0]),"r"(a[1]),"r"(a[2]),"r"(a[3]), "r"(b0),"r"(b1));
}
#define CPA(dst,src) asm volatile("cp.async.cg.shared.global [%0], [%1], 16;" :: "r"(dst),"l"(src))
#define CPC() asm volatile("cp.async.commit_group;" ::: "memory")
#define CPW(n) asm volatile("cp.async.wait_group %0;" :: "n"(n) : "memory")

__device__ __forceinline__ uint32_t cvt2h(float x, float y){
    __half2 h = __floats2half2_rn(x,y);
    return *(uint32_t*)&h;
}
__device__ __forceinline__ void split_pair(float x, float y, uint32_t& hi, uint32_t& lo){
    __half2 h = __floats2half2_rn(x,y);
    float2 f = __half22float2(h);
    __half2 l = __floats2half2_rn(x - f.x, y - f.y);
    hi = *(uint32_t*)&h; lo = *(uint32_t*)&l;
}

// ---------------- prep: hi/lo W^T + folded Weff^T ----------------
__global__ void k_prep(const float* __restrict__ Wq, const float* __restrict__ Wk,
                       const float* __restrict__ Wv, const float* __restrict__ Wout){
    int idx = blockIdx.x*256 + threadIdx.x;   // 262144
    if (idx < 3*65536) {
        int w = idx >> 16, r = idx & 65535, n = r >> 10, k = r & 1023;
        const float* W = w==0 ? Wq : (w==1 ? Wk : Wv);
        float x = W[k*DD + n];
        __half h = __float2half(x);
        g_WTh[idx] = h;
        g_WTl[idx] = __float2half(x - __half2float(h));
    } else {
        int r = idx - 3*65536, j = r >> 6, d = r & 63;
        float s = 0.f;
#pragma unroll
        for (int h = 0; h < 16; ++h) s += Wout[(h*DD + d)*HH + j];
        __half hh = __float2half(s);
        g_WeffTh[j*DD + d] = hh;
        g_WeffTl[j*DD + d] = __float2half(s - __half2float(hh));
    }
}

// ---------------- projection via mma + fused Gram (sel==1) ----------------
#define PP 40   // pitch in halves (80 B)
__global__ __launch_bounds__(256) void k_proj_mma(
    const float* __restrict__ Xq, const float* __restrict__ Xk, const float* __restrict__ Xv,
    const float* __restrict__ bq, const float* __restrict__ bk, const float* __restrict__ bv)
{
    __shared__ __align__(16) char pbuf[33536];
    __half* Xh = (__half*)pbuf;
    __half* Wh = (__half*)(pbuf + 10240);
    __half* Wl = (__half*)(pbuf + 15360);
    float*  Ks2 = (float*)pbuf;

    const int t = threadIdx.x, w = t>>5, lane = t&31;
    const int sel = blockIdx.y, m0 = blockIdx.x*128;
    const int wm = w&3, wn = w>>2;
    const float* X    = sel==0?Xq:(sel==1?Xk:Xv);
    const float* bias = sel==0?bq:(sel==1?bk:bv);
    const __half* WTh = g_WTh + sel*65536;
    const __half* WTl = g_WTl + sel*65536;

    const int i8 = lane&7, q4 = lane>>3;
    const int mrow = i8 + ((q4&1)<<3), kcol = (q4>>1)<<3;
    const int s2 = (lane>>3)&1;
    const uint32_t xh_b = su32(Xh), wh_b = su32(Wh), wl_b = su32(Wl);

    float acc[2][4][4];
#pragma unroll
    for (int a=0;a<2;++a)
#pragma unroll
        for (int bq_=0;bq_<4;++bq_)
#pragma unroll
            for (int cq=0;cq<4;++cq) acc[a][bq_][cq]=0.f;

    float4 xr[4]; uint4 whr, wlr;
    auto LD = [&](int c){
        int k0 = c*32;
#pragma unroll
        for (int i=0;i<4;++i){ int id=t+i*256, row=id>>3, c4=id&7;
            xr[i] = *(const float4*)&X[(size_t)(m0+row)*HH + k0 + c4*4]; }
        { int row = t>>2, cc = t&3;
          whr = *(const uint4*)(WTh + (size_t)row*HH + k0 + cc*8);
          wlr = *(const uint4*)(WTl + (size_t)row*HH + k0 + cc*8); }
    };
    auto ST = [&](){
#pragma unroll
        for (int i=0;i<4;++i){ int id=t+i*256, row=id>>3, c4=id&7;
            *(uint2*)&Xh[row*PP + c4*4] =
                make_uint2(cvt2h(xr[i].x, xr[i].y), cvt2h(xr[i].z, xr[i].w)); }
        { int row = t>>2, cc = t&3;
          *(uint4*)&Wh[row*PP + cc*8] = whr;
          *(uint4*)&Wl[row*PP + cc*8] = wlr; }
    };

    LD(0); ST(); __syncthreads();
    for (int c=0;c<32;++c){
        if (c<31) LD(c+1);
#pragma unroll
        for (int ks=0;ks<2;++ks){
            uint32_t ah[2][4];
#pragma unroll
            for (int mt=0;mt<2;++mt){
                uint32_t ra = (uint32_t)(((wm*32+mt*16+mrow)*PP + ks*16 + kcol)*2);
                ldsm4(ah[mt][0],ah[mt][1],ah[mt][2],ah[mt][3], xh_b + ra);
            }
#pragma unroll
            for (int nt=0;nt<4;++nt){
                uint32_t rb = (uint32_t)(((wn*32+nt*8+i8)*PP + ks*16 + s2*8)*2);
                uint32_t bh0,bh1,bl0,bl1;
                ldsm2(bh0,bh1, wh_b + rb);
                ldsm2(bl0,bl1, wl_b + rb);
#pragma unroll
                for (int mt=0;mt<2;++mt){
                    mma16816(acc[mt][nt], ah[mt], bh0, bh1);
                    mma16816(acc[mt][nt], ah[mt], bl0, bl1);
                }
            }
        }
        __syncthreads();
        if (c<31){ ST(); __syncthreads(); }
    }

    // epilogue: q,k,v -> f16 ; k also stages fp32 for Gram
    const int g4 = lane>>2, tq = lane&3;
#pragma unroll
    for (int mt=0;mt<2;++mt)
#pragma unroll
    for (int nt=0;nt<4;++nt){
        int n = wn*32 + nt*8 + tq*2;
        float2 bb = __ldg((const float2*)&bias[n]);
#pragma unroll
        for (int hf=0;hf<2;++hf){
            int rowl = wm*32 + mt*16 + g4 + hf*8;
            float v0 = acc[mt][nt][hf*2+0] + bb.x;
            float v1 = acc[mt][nt][hf*2+1] + bb.y;
            size_t o = (size_t)(m0 + rowl)*DD + n;
            if (sel == 0){
                *(uint32_t*)(g_qh + o) = cvt2h(v0, v1);
            } else if (sel == 1){
                *(uint32_t*)(g_kh + o) = cvt2h(v0, v1);
                Ks2[rowl*65 + n]   = v0;
                Ks2[rowl*65 + n+1] = v1;
            } else {
                *(uint32_t*)(g_vh + o) = cvt2h(v0, v1);
            }
        }
    }

    if (sel == 1){
        __syncthreads();
        int a = t >> 2, b0 = (t & 3) * 16;
        float gacc[16];
#pragma unroll
        for (int i = 0; i < 16; ++i) gacc[i] = 0.f;
        for (int j = 0; j < 128; ++j) {
            float ka = Ks2[j*65 + a];
#pragma unroll
            for (int bb = 0; bb < 16; ++bb) gacc[bb] += ka * Ks2[j*65 + b0 + bb];
        }
        int bB = m0 >> 11, cb = (m0 >> 7) & 15;
        float* gp = g_Gpart + (size_t)(bB*16 + cb)*4096;
#pragma unroll
        for (int bb = 0; bb < 16; ++bb) gp[a*64 + b0 + bb] = gacc[bb];
        if (t < 64) {
            float s = 0.f;
            for (int j = 0; j < 128; ++j) s += Ks2[j*65 + t];
            g_Kspart[(bB*16 + cb)*64 + t] = s;
        }
    }
}

// ---------------- Gram reduce ----------------
__global__ void k_gramred() {
    int idx = blockIdx.x * 256 + threadIdx.x;
    if (idx < BB*4096) {
        int b = idx >> 12, e = idx & 4095;
        float s = 0.f;
#pragma unroll
        for (int c = 0; c < 16; ++c) s += g_Gpart[(size_t)(b*16+c)*4096 + e];
        g_G[idx] = s;
    } else if (idx < BB*4096 + BB*64) {
        int r = idx - BB*4096, b = r >> 6, e = r & 63;
        float s = 0.f;
#pragma unroll
        for (int c = 0; c < 16; ++c) s += g_Kspart[(b*16+c)*64 + e];
        g_Ksum[r] = s;
    }
}

// ---------------- fused flash attention + stats + output GEMM ----------------
// 512 threads, 16 warps: wm=w&1 (32-row half), wn=w>>1 (16-key / 16-col slice)
// smem map (bytes):
#define OQH 0u
#define OQL 9216u
#define OC0 18432u
#define OC1 18688u
#define ORED 18944u         // 8*64 floats = 2048
#define OKV 21504u
#define KVB 36864u          // per buffer: Kh +0, Vh +18432
#define ATTN_SMEM (OKV + 2*KVB)   // 95232
#define AP 72               // pitch in halves (144 B)

__global__ __launch_bounds__(512) void k_attn_mma(const float* __restrict__ bout,
                                                  float* __restrict__ out)
{
    extern __shared__ __align__(16) char smc[];
    const uint32_t sb = su32(smc);
    const int t = threadIdx.x, w = t>>5, lane = t&31;
    const int b = blockIdx.y, qbase = blockIdx.x*64;
    const int wm = w&1, wn = w>>1;         // wn in 0..7
    const int i8 = lane&7, q4 = lane>>3;
    const int mrow = i8 + ((q4&1)<<3), kcol = (q4>>1)<<3;
    const int s2 = (lane>>3)&1;
    const int g4 = lane>>2, tq = lane&3;

    auto issue = [&](int kc, int bf){
        uint32_t dbase = sb + OKV + (uint32_t)bf*KVB;
        size_t g0 = ((size_t)b*SQ + (size_t)kc*128)*DD;
#pragma unroll
        for (int i=0;i<2;++i){
            int id = t + i*512, row = id>>3, c = id&7;
            uint32_t doff = (uint32_t)(row*144 + c*16);
            size_t so = g0 + (size_t)row*DD + c*8;
            CPA(dbase + doff,          g_kh + so);
            CPA(dbase + 18432u + doff, g_vh + so);
        }
        CPC();
    };
    issue(0, 0);

    // Q tile (f16, 64 rows)
    {
        int row = t>>3, c = t&7;
        size_t so = ((size_t)(b*SQ + qbase) + row)*DD + c*8;
        *(uint4*)(smc + OQH + row*144 + c*16) = *(const uint4*)(g_qh + so);
    }
    // stats inputs in KV buffer 1: G[4096] floats, then qf32[64][68]
    float* Gs  = (float*)(smc + OKV + KVB);
    float* qf  = (float*)(smc + OKV + KVB + 16384u);
    float* Ksm = (float*)(smc + ORED);
    for (int id = t; id < 1024; id += 512)
        *(float4*)&Gs[id*4] = *(const float4*)&g_G[(size_t)b*4096 + id*4];
    if (t < 64) Ksm[t] = g_Ksum[b*64 + t];
    __syncthreads();
    for (int id = t; id < 2048; id += 512){
        int row = id >> 5, d2 = (id & 31) * 2;
        __half2 h = *(__half2*)(smc + OQH + row*144 + d2*2);
        float2 fh = __half22float2(h);
        qf[row*68 + d2]   = fh.x;
        qf[row*68 + d2+1] = fh.y;
    }
    __syncthreads();
    if (t < 256){
        int q = t >> 2, seg = (t & 3) * 16;
        float su = 0.f, sq = 0.f;
        for (int a = seg; a < seg+16; ++a) {
            float qa = qf[q*68 + a];
            su += qa * Ksm[a];
            float ta = 0.f;
#pragma unroll 16
            for (int bb = 0; bb < 64; ++bb) ta += Gs[a*64 + bb] * qf[q*68 + bb];
            sq += qa * ta;
        }
        su += __shfl_xor_sync(0xffffffffu, su, 1);
        su += __shfl_xor_sync(0xffffffffu, su, 2);
        sq += __shfl_xor_sync(0xffffffffu, sq, 1);
        sq += __shfl_xor_sync(0xffffffffu, sq, 2);
        if ((t & 3) == 0){
            float mu  = su * (1.f/(32.f*(float)SQ));
            float var = (sq*(1.f/1024.f) - (float)SQ*mu*mu) * (1.f/((float)SQ - 1.f));
            float rinv = 1.f / (sqrtf(var) + 1e-8f);
            ((float*)(smc+OC1))[q] = rinv * (1.f/32.f);
            ((float*)(smc+OC0))[q] = -mu * rinv;
        }
    }
    __syncthreads();
    float c0v[2][2], c1v[2][2];
#pragma unroll
    for (int mt=0;mt<2;++mt)
#pragma unroll
        for (int hf=0;hf<2;++hf){
            int row = wm*32 + mt*16 + g4 + hf*8;
            c0v[mt][hf] = ((float*)(smc+OC0))[row];
            c1v[mt][hf] = ((float*)(smc+OC1))[row];
        }

    float oc[2][8][4];
#pragma unroll
    for (int a=0;a<2;++a)
#pragma unroll
        for (int n=0;n<8;++n)
#pragma unroll
            for (int c=0;c<4;++c) oc[a][n][c]=0.f;
    float lacc[4] = {0.f,0.f,0.f,0.f};

    for (int kc=0;kc<16;++kc){
        if (kc<15){ issue(kc+1, (kc+1)&1); CPW(1); } else { CPW(0); }
        __syncthreads();
        const uint32_t kb = sb + OKV + (uint32_t)((kc&1)*KVB);

        // S = Q K^T  (warp: 32 rows x 16 keys, 1 MMA per tile)
        float sa[2][2][4];
#pragma unroll
        for (int a=0;a<2;++a)
#pragma unroll
            for (int n=0;n<2;++n)
#pragma unroll
                for (int c=0;c<4;++c) sa[a][n][c]=0.f;
#pragma unroll
        for (int ks=0;ks<4;++ks){
            uint32_t ah[2][4];
#pragma unroll
            for (int mt=0;mt<2;++mt){
                uint32_t ra = (uint32_t)(((wm*32+mt*16+mrow)*AP + ks*16 + kcol)*2);
                ldsm4(ah[mt][0],ah[mt][1],ah[mt][2],ah[mt][3], sb + OQH + ra);
            }
#pragma unroll
            for (int nt=0;nt<2;++nt){
                uint32_t rb = kb + (uint32_t)(((wn*16+nt*8+i8)*AP + ks*16 + s2*8)*2);
                uint32_t bh0,bh1;
                ldsm2(bh0,bh1, rb);
#pragma unroll
                for (int mt=0;mt<2;++mt)
                    mma16816(sa[mt][nt], ah[mt], bh0, bh1);
            }
        }
        // p = exp(s*c1 + c0), rowsum
#pragma unroll
        for (int mt=0;mt<2;++mt)
#pragma unroll
        for (int nt=0;nt<2;++nt){
            float* s4 = sa[mt][nt];
            s4[0] = __expf(fmaf(s4[0], c1v[mt][0], c0v[mt][0]));
            s4[1] = __expf(fmaf(s4[1], c1v[mt][0], c0v[mt][0]));
            s4[2] = __expf(fmaf(s4[2], c1v[mt][1], c0v[mt][1]));
            s4[3] = __expf(fmaf(s4[3], c1v[mt][1], c0v[mt][1]));
            lacc[mt*2+0] += s4[0]+s4[1];
            lacc[mt*2+1] += s4[2]+s4[3];
        }
        // O += P V  (warp: its 16 keys x all 64 d)
        {
            uint32_t pah[2][4];
#pragma unroll
            for (int mt=0;mt<2;++mt){
                pah[mt][0] = cvt2h(sa[mt][0][0], sa[mt][0][1]);
                pah[mt][1] = cvt2h(sa[mt][0][2], sa[mt][0][3]);
                pah[mt][2] = cvt2h(sa[mt][1][0], sa[mt][1][1]);
                pah[mt][3] = cvt2h(sa[mt][1][2], sa[mt][1][3]);
            }
#pragma unroll
            for (int nt=0;nt<8;++nt){
                uint32_t va = kb + 18432u +
                    (uint32_t)(((wn*16 + i8 + s2*8)*AP + nt*8)*2);
                uint32_t bh0,bh1;
                ldsm2t(bh0,bh1, va);
#pragma unroll
                for (int mt=0;mt<2;++mt)
                    mma16816(oc[mt][nt], pah[mt], bh0, bh1);
            }
        }
        __syncthreads();
    }

    // rowsum reduce across quad, write per-wn partials
#pragma unroll
    for (int i=0;i<4;++i){
        lacc[i] += __shfl_xor_sync(0xffffffffu, lacc[i], 1);
        lacc[i] += __shfl_xor_sync(0xffffffffu, lacc[i], 2);
    }
    if (tq == 0){
#pragma unroll
        for (int mt=0;mt<2;++mt)
#pragma unroll
            for (int hf=0;hf<2;++hf)
                ((float*)(smc+ORED))[wn*64 + wm*32 + mt*16 + g4 + hf*8] = lacc[mt*2+hf];
    }
    // partial O -> smem, two passes (8 wn groups into 4 buffers)
    {
        float* ob = (float*)(smc + OKV + (size_t)(wn&3)*17408);
        if (wn < 4){
#pragma unroll
            for (int mt=0;mt<2;++mt)
#pragma unroll
            for (int nt=0;nt<8;++nt){
                int r0 = wm*32 + mt*16 + g4, cc = nt*8 + tq*2;
                *(float2*)&ob[r0*68 + cc]     = make_float2(oc[mt][nt][0], oc[mt][nt][1]);
                *(float2*)&ob[(r0+8)*68 + cc] = make_float2(oc[mt][nt][2], oc[mt][nt][3]);
            }
        }
        __syncthreads();
        if (wn >= 4){
#pragma unroll
            for (int mt=0;mt<2;++mt)
#pragma unroll
            for (int nt=0;nt<8;++nt){
                int r0 = wm*32 + mt*16 + g4, cc = nt*8 + tq*2;
                float2 a0 = *(float2*)&ob[r0*68 + cc];
                float2 a1 = *(float2*)&ob[(r0+8)*68 + cc];
                *(float2*)&ob[r0*68 + cc]     = make_float2(a0.x + oc[mt][nt][0], a0.y + oc[mt][nt][1]);
                *(float2*)&ob[(r0+8)*68 + cc] = make_float2(a1.x + oc[mt][nt][2], a1.y + oc[mt][nt][3]);
            }
        }
    }
    __syncthreads();
    if (t < 64){
        float s = 0.f;
#pragma unroll
        for (int wq=0;wq<8;++wq) s += ((float*)(smc+ORED))[wq*64 + t];
        ((float*)(smc+OC0))[t] = 1.f / s;
    }
    __syncthreads();
    // head = (sum of 4 ob) * linv -> f16 hi/lo in OQH/OQL
    for (int id = t; id < 2048; id += 512){
        int row = id >> 5, d2 = (id & 31) * 2;
        float o0 = 0.f, o1 = 0.f;
#pragma unroll
        for (int wq=0;wq<4;++wq){
            const float* ob = (const float*)(smc + OKV + (size_t)wq*17408);
            o0 += ob[row*68 + d2];
            o1 += ob[row*68 + d2 + 1];
        }
        float li = ((float*)(smc+OC0))[row];
        uint32_t hi, lo;
        split_pair(o0*li, o1*li, hi, lo);
        *(uint32_t*)(smc + OQH + row*144 + d2*2) = hi;
        *(uint32_t*)(smc + OQL + row*144 + d2*2) = lo;
    }

    // fused output GEMM: out = head @ Weff + bout  (head hi/lo 3 MMAs)
    float* stage = (float*)(smc + OKV + KVB);   // 64 x 132 floats
    float* orow = out + (size_t)(b*SQ + qbase)*HH;
    for (int jt=0;jt<8;++jt){
        __syncthreads();
#pragma unroll
        for (int i=0;i<2;++i){
            int id = t + i*512, row = id>>3, c = id&7;
            size_t so = (size_t)(jt*128 + row)*DD + c*8;
            *(uint4*)(smc + OKV + row*144 + c*16)          = *(const uint4*)(g_WeffTh + so);
            *(uint4*)(smc + OKV + 18432u + row*144 + c*16) = *(const uint4*)(g_WeffTl + so);
        }
        __syncthreads();
        float acc[2][2][4];
#pragma unroll
        for (int a=0;a<2;++a)
#pragma unroll
            for (int n=0;n<2;++n)
#pragma unroll
                for (int c=0;c<4;++c) acc[a][n][c]=0.f;
#pragma unroll
        for (int ks=0;ks<4;++ks){
            uint32_t ah[2][4], al[2][4];
#pragma unroll
            for (int mt=0;mt<2;++mt){
                uint32_t ra = (uint32_t)(((wm*32+mt*16+mrow)*AP + ks*16 + kcol)*2);
                ldsm4(ah[mt][0],ah[mt][1],ah[mt][2],ah[mt][3], sb + OQH + ra);
                ldsm4(al[mt][0],al[mt][1],al[mt][2],al[mt][3], sb + OQL + ra);
            }
#pragma unroll
            for (int nt=0;nt<2;++nt){
                uint32_t rb = sb + OKV + (uint32_t)(((wn*16+nt*8+i8)*AP + ks*16 + s2*8)*2);
                uint32_t bh0,bh1,bl0,bl1;
                ldsm2(bh0,bh1, rb);
                ldsm2(bl0,bl1, rb + 18432u);
#pragma unroll
                for (int mt=0;mt<2;++mt){
                    mma16816(acc[mt][nt], ah[mt], bh0, bh1);
                    mma16816(acc[mt][nt], ah[mt], bl0, bl1);
                    mma16816(acc[mt][nt], al[mt], bh0, bh1);
                }
            }
        }
        // stage 64x128 with bias (pitch 132)
#pragma unroll
        for (int mt=0;mt<2;++mt)
#pragma unroll
        for (int nt=0;nt<2;++nt){
            int colL = wn*16 + nt*8 + tq*2;
            float2 bb = __ldg((const float2*)&bout[jt*128 + colL]);
#pragma unroll
            for (int hf=0;hf<2;++hf){
                int row = wm*32 + mt*16 + g4 + hf*8;
                *(float2*)&stage[row*132 + colL] =
                    make_float2(acc[mt][nt][hf*2+0] + bb.x, acc[mt][nt][hf*2+1] + bb.y);
            }
        }
        __syncthreads();
#pragma unroll
        for (int i=0;i<4;++i){
            int id = t + i*512, row = id>>5, c4 = (id&31)*4;
            *(float4*)&orow[(size_t)row*HH + jt*128 + c4] = *(float4*)&stage[row*132 + c4];
        }
    }
}

// ---------------------------------------------------------------------------
extern "C" void kernel_launch(void* const* d_in, const int* in_sizes, int n_in,
                              void* d_out, int out_size)
{
    (void)in_sizes; (void)n_in; (void)out_size;
    const float* query = (const float*)d_in[0];
    const float* key   = (const float*)d_in[1];
    const float* value = (const float*)d_in[2];
    const float* Wq   = (const float*)d_in[4];
    const float* bq   = (const float*)d_in[5];
    const float* Wk   = (const float*)d_in[6];
    const float* bk   = (const float*)d_in[7];
    const float* Wv   = (const float*)d_in[8];
    const float* bv   = (const float*)d_in[9];
    const float* Wout = (const float*)d_in[10];
    const float* bo   = (const float*)d_in[11];
    float* out = (float*)d_out;

    cudaFuncSetAttribute(k_attn_mma, cudaFuncAttributeMaxDynamicSharedMemorySize, ATTN_SMEM);

    k_prep<<<1024, 256>>>(Wq, Wk, Wv, Wout);
    k_proj_mma<<<dim3(64,3), 256>>>(query, key, value, bq, bk, bv);
    k_gramred<<<66, 256>>>();
    k_attn_mma<<<dim3(32,BB), 512, ATTN_SMEM>>>(bo, out);
}